// round 13
// baseline (speedup 1.0000x reference)
#include <cuda_runtime.h>
#include <cstdint>

#define BATCH 16
#define NSEQ  1024
#define NTOK  2048
#define DM    256
#define NLAYER 4
#define NSTATE 8
#define NF    16
#define CIN   33
#define LN_EPS 1e-5f
#define SEGSZ (BATCH*NSEQ*DM)

// ---------------- scratch ----------------
__device__ float g_seq [BATCH*NTOK*DM];
__device__ float g_xn  [BATCH*NTOK*DM];
__device__ float g_gate[BATCH*NTOK*DM];
__device__ float g_bu  [BATCH*NSTATE*NTOK];
__device__ float g_hs  [BATCH*NSTATE*NTOK];
__device__ float g_qkv [3*SEGSZ];
__device__ float g_att [BATCH*NSEQ*DM];
__device__ float g_wc  [DM*DM];
__device__ float g_bc  [DM];
__device__ unsigned g_wh[294912];
__device__ unsigned g_wl[294912];

#define OFF_GATE   0
#define OFF_INPROJ 131072
#define OFF_DEC    262144

// ---------------- bf16 split helpers ----------------
__device__ __forceinline__ unsigned packbf(float x0, float x1) {
    unsigned r;
    asm("cvt.rn.bf16x2.f32 %0, %1, %2;" : "=r"(r) : "f"(x1), "f"(x0));
    return r;
}
__device__ __forceinline__ void split2(float x0, float x1, unsigned& h, unsigned& l) {
    h = packbf(x0, x1);
    float h0 = __uint_as_float(h << 16);
    float h1 = __uint_as_float(h & 0xFFFF0000u);
    l = packbf(x0 - h0, x1 - h1);
}
__device__ __forceinline__ void mma16(float (&d)[4], const unsigned* a, const unsigned* b) {
    asm volatile("mma.sync.aligned.m16n8k16.row.col.f32.bf16.bf16.f32 "
        "{%0,%1,%2,%3}, {%4,%5,%6,%7}, {%8,%9}, {%0,%1,%2,%3};"
        : "+f"(d[0]), "+f"(d[1]), "+f"(d[2]), "+f"(d[3])
        : "r"(a[0]), "r"(a[1]), "r"(a[2]), "r"(a[3]), "r"(b[0]), "r"(b[1]));
}
__device__ __forceinline__ void cpa16(unsigned s, const void* g) {
    asm volatile("cp.async.cg.shared.global [%0], [%1], 16;" :: "r"(s), "l"(g));
}
#define CP_COMMIT() asm volatile("cp.async.commit_group;")
#define CP_WAIT0()  asm volatile("cp.async.wait_group 0;")
#define CP_WAIT1()  asm volatile("cp.async.wait_group 1;")

// ---------------- weight pack ----------------
__global__ void pack_kernel(const float* __restrict__ src,
                            unsigned* __restrict__ dh, unsigned* __restrict__ dl,
                            int npairs)
{
    int i = blockIdx.x*256 + threadIdx.x;
    if (i < npairs) {
        float2 v = ((const float2*)src)[i];
        unsigned h, l; split2(v.x, v.y, h, l);
        dh[i] = h; dl[i] = l;
    }
}

// ---------------- combine out_w into dec_w1 (+ bias fold) ----------------
__global__ void comb_wb_kernel(const float* __restrict__ w1,
                               const float* __restrict__ ow,
                               const float* __restrict__ ob,
                               const float* __restrict__ b1,
                               float* __restrict__ wc,
                               float* __restrict__ bc)
{
    __shared__ float row[DM];
    __shared__ float red[8];
    int i = blockIdx.x, j = threadIdx.x;
    row[j] = w1[i*DM + j];
    __syncthreads();
    float s = 0.f;
    #pragma unroll 8
    for (int k = 0; k < DM; k++) s += row[k] * ow[k*DM + j];
    wc[i*DM + j] = s;

    float p = row[j] * ob[j];
    #pragma unroll
    for (int o = 16; o; o >>= 1) p += __shfl_xor_sync(0xffffffffu, p, o);
    if ((j & 31) == 0) red[j >> 5] = p;
    __syncthreads();
    if (j == 0) {
        float t = b1[i];
        #pragma unroll
        for (int k = 0; k < 8; k++) t += red[k];
        bc[i] = t;
    }
}

// ---------------- LN + Bu core ----------------
__device__ __forceinline__ void ln_bu_body(float x, int token, int tid,
                                           const float* __restrict__ lng,
                                           const float* __restrict__ lnb,
                                           const float* __restrict__ Bw,
                                           float* __restrict__ xn_out,
                                           float* __restrict__ bu_out,
                                           float* xs, float* part)
{
    int w = tid >> 5, lane = tid & 31;
    float s = x;
    #pragma unroll
    for (int o = 16; o; o >>= 1) s += __shfl_xor_sync(0xffffffffu, s, o);
    if (lane == 0) part[w] = s;
    __syncthreads();
    float mu = 0.f;
    #pragma unroll
    for (int i = 0; i < 8; i++) mu += part[i];
    mu *= (1.f/256.f);
    float dx = x - mu;
    float s2 = dx*dx;
    #pragma unroll
    for (int o = 16; o; o >>= 1) s2 += __shfl_xor_sync(0xffffffffu, s2, o);
    __syncthreads();
    if (lane == 0) part[8 + w] = s2;
    __syncthreads();
    float var = 0.f;
    #pragma unroll
    for (int i = 0; i < 8; i++) var += part[8 + i];
    var *= (1.f/256.f);

    float xn = dx * rsqrtf(var + LN_EPS) * lng[tid] + lnb[tid];
    xn_out[(size_t)token*DM + tid] = xn;
    xs[tid] = xn;
    __syncthreads();

    float bs = 0.f;
    #pragma unroll
    for (int i = 0; i < 8; i++) {
        int d = lane + i*32;
        bs += xs[d] * Bw[w*DM + d];
    }
    #pragma unroll
    for (int o = 16; o; o >>= 1) bs += __shfl_xor_sync(0xffffffffu, bs, o);
    if (lane == 0) {
        int b = token >> 11, n = token & 2047;
        bu_out[((size_t)(b*NSTATE + w))*NTOK + n] = bs;
    }
}

// ---------------- fused embed + LN + Bu ----------------
__global__ void embed_ln_bu_kernel(const float* __restrict__ sparse_coords,
                                   const float* __restrict__ sparse_values,
                                   const float* __restrict__ query_coords,
                                   const float* __restrict__ t_in,
                                   const float* __restrict__ noise,
                                   const float* __restrict__ B_f,
                                   const float* __restrict__ Wq, const float* __restrict__ bq,
                                   const float* __restrict__ Wi, const float* __restrict__ bi,
                                   const float* __restrict__ lng, const float* __restrict__ lnb,
                                   const float* __restrict__ Bw,
                                   float* __restrict__ seq,
                                   float* __restrict__ xn_out, float* __restrict__ bu_out)
{
    __shared__ float feat[CIN];
    __shared__ float xs[DM];
    __shared__ float part[16];
    int token = blockIdx.x;
    int b = token / NTOK;
    int n = token % NTOK;
    int tid = threadIdx.x;

    const float* W; const float* bias;
    float cx, cy, val;
    if (n < NSEQ) {
        cx = sparse_coords[(b*NSEQ + n)*2 + 0];
        cy = sparse_coords[(b*NSEQ + n)*2 + 1];
        val = sparse_values[b*NSEQ + n];
        W = Wi; bias = bi;
    } else {
        int m = n - NSEQ;
        cx = query_coords[(b*NSEQ + m)*2 + 0];
        cy = query_coords[(b*NSEQ + m)*2 + 1];
        val = noise[b*NSEQ + m];
        W = Wq; bias = bq;
    }
    if (tid < NF) {
        float proj = cx * B_f[tid] + cy * B_f[NF + tid];
        feat[tid]      = sinf(proj);
        feat[NF + tid] = cosf(proj);
    }
    if (tid == 0) feat[2*NF] = val;
    __syncthreads();

    int d = tid;
    float acc = bias[d];
    const float* wrow = W + d*CIN;
    #pragma unroll
    for (int k = 0; k < CIN; k++) acc += feat[k] * wrow[k];

    float tv = t_in[b];
    float e;
    if (d < 128) e = sinf(tv * expf((float)d * (-9.210340371976184f / 127.f)));
    else         e = cosf(tv * expf((float)(d-128) * (-9.210340371976184f / 127.f)));

    float x = acc + e;
    seq[(size_t)token*DM + d] = x;
    __syncthreads();
    ln_bu_body(x, token, tid, lng, lnb, Bw, xn_out, bu_out, xs, part);
}

// ---------------- fused: ssm_out(l) + ln_bu(l+1) ----------------
__global__ void ssm_ln_bu_kernel(const float* __restrict__ Cw, const float* __restrict__ Dp,
                                 const float* __restrict__ xn, const float* __restrict__ hs,
                                 const float* __restrict__ gate, float* __restrict__ seq,
                                 const float* __restrict__ lng2, const float* __restrict__ lnb2,
                                 const float* __restrict__ Bw2,
                                 float* __restrict__ xn_out, float* __restrict__ bu_out)
{
    __shared__ float xs[DM];
    __shared__ float part[16];
    __shared__ float hsl[NSTATE];
    int token = blockIdx.x;
    int tid = threadIdx.x;
    if (tid < NSTATE) {
        int b = token >> 11, n = token & 2047;
        hsl[tid] = hs[((size_t)(b*NSTATE + tid))*NTOK + n];
    }
    __syncthreads();
    size_t idx = (size_t)token*DM + tid;
    float xv = xn[idx];
    float o = Dp[tid] * xv;
    #pragma unroll
    for (int s = 0; s < NSTATE; s++) o += hsl[s] * Cw[tid*NSTATE + s];
    float x = seq[idx] + gate[idx] * o;
    seq[idx] = x;
    __syncthreads();
    ln_bu_body(x, token, tid, lng2, lnb2, Bw2, xn_out, bu_out, xs, part);
}

// ---------------- last-layer ssm_out ----------------
__global__ void ssm_out_kernel(const float* __restrict__ Cw, const float* __restrict__ Dp,
                               const float* __restrict__ xn, const float* __restrict__ hs,
                               const float* __restrict__ gate, float* __restrict__ seq)
{
    int token = blockIdx.x;
    int tid = threadIdx.x;
    __shared__ float hsl[NSTATE];
    if (tid < NSTATE) {
        int b = token >> 11, n = token & 2047;
        hsl[tid] = hs[((size_t)(b*NSTATE + tid))*NTOK + n];
    }
    __syncthreads();
    size_t idx = (size_t)token*DM + tid;
    float xv = xn[idx];
    float o = Dp[tid] * xv;
    #pragma unroll
    for (int s = 0; s < NSTATE; s++) o += hsl[s] * Cw[tid*NSTATE + s];
    seq[idx] += gate[idx] * o;
}

// ---------------- scan ----------------
__global__ void scan_kernel(const float* __restrict__ A_log,
                            const float* __restrict__ bu, float* __restrict__ hs)
{
    __shared__ float sb[NTOK];
    int wi = blockIdx.x;
    int lane = threadIdx.x;
    int s = wi & 7;

    float A = -fminf(fmaxf(expf(A_log[s]), 1e-8f), 10.f);
    float Abar = expf(A * (1.f/2048.f));
    float p64  = expf(A * (1.f/32.f));

    const float* bup = bu + (size_t)wi*NTOK;
    float* hsp = hs + (size_t)wi*NTOK;

    #pragma unroll
    for (int i = 0; i < 64; i++) sb[lane + i*32] = bup[lane + i*32];
    __syncwarp();

    int base = lane * 64;
    float loc = 0.f;
    #pragma unroll 8
    for (int i = 0; i < 64; i++) loc = Abar*loc + sb[base + i];

    float aa = p64, bb = loc;
    #pragma unroll
    for (int off = 1; off < 32; off <<= 1) {
        float pa = __shfl_up_sync(0xffffffffu, aa, off);
        float pb = __shfl_up_sync(0xffffffffu, bb, off);
        if (lane >= off) { bb = aa*pb + bb; aa = aa*pa; }
    }
    float hin = __shfl_up_sync(0xffffffffu, bb, 1);
    if (lane == 0) hin = 0.f;

    float h = hin;
    #pragma unroll 8
    for (int i = 0; i < 64; i++) {
        h = Abar*h + sb[base + i];
        sb[base + i] = h;
    }
    __syncwarp();
    #pragma unroll
    for (int i = 0; i < 64; i++) hsp[lane + i*32] = sb[lane + i*32];
}

// ---------------- tensor-core GEMM (bf16x3, pre-packed B) ----------------
// act: 0=none 1=sigmoid 3=relu+dot(w2)->atomicAdd  4=fused qkv (N=768)
#define GSK 24
#define BSP 12
__global__ __launch_bounds__(256, 2)
void gemm_tc(const float* __restrict__ A,
             const unsigned* __restrict__ Wh, const unsigned* __restrict__ Wl,
             const float* __restrict__ bias, float* __restrict__ C,
             const float* __restrict__ w2,
             int rpb, int tstride, int rowoff, int act)
{
    __shared__ float As[2][128*GSK];
    __shared__ unsigned sBh[2][128*BSP];
    __shared__ unsigned sBl[2][128*BSP];

    int tid = threadIdx.x;
    int m0 = blockIdx.y * 128, n0 = blockIdx.x * 128;

    float* Cb = C;
    int rowoff_eff = rowoff;
    if (act == 4) {
        int seg = n0 >> 8;                 // 0=q 1=k 2=v
        rowoff_eff = (seg == 0) ? NSEQ : 0;
        Cb = C + (size_t)seg * SEGSZ;
    }

    int r  = tid >> 1;
    int cb = (tid & 1) * 8;
    int h4 = (tid & 1) * 4;
    int m = m0 + r;
    int tok = (m / rpb) * tstride + rowoff_eff + (m % rpb);
    const float*    Aptr  = A  + (size_t)tok*DM + cb;
    const unsigned* Bptrh = Wh + (size_t)(n0 + r)*128 + h4;
    const unsigned* Bptrl = Wl + (size_t)(n0 + r)*128 + h4;

    int w = tid >> 5, lane = tid & 31;
    int g = lane >> 2, t = lane & 3;
    int wm = w >> 1, wn = w & 1;

    float acc[2][8][4] = {};

    {
        float4 a0 = *(const float4*)Aptr;
        float4 a1 = *(const float4*)(Aptr + 4);
        uint4  b0 = *(const uint4*)Bptrh;
        uint4  b1 = *(const uint4*)Bptrl;
        *(float4*)&As[0][r*GSK + cb]     = a0;
        *(float4*)&As[0][r*GSK + cb + 4] = a1;
        *(uint4*)&sBh[0][r*BSP + h4] = b0;
        *(uint4*)&sBl[0][r*BSP + h4] = b1;
    }
    __syncthreads();

    #pragma unroll 1
    for (int ck = 0; ck < 16; ck++) {
        int buf = ck & 1;
        float4 a0, a1; uint4 nb0, nb1;
        if (ck < 15) {
            a0  = *(const float4*)(Aptr + (ck+1)*16);
            a1  = *(const float4*)(Aptr + (ck+1)*16 + 4);
            nb0 = *(const uint4*)(Bptrh + (ck+1)*8);
            nb1 = *(const uint4*)(Bptrl + (ck+1)*8);
        }

        unsigned ah[2][4], al[2][4];
        #pragma unroll
        for (int mt = 0; mt < 2; mt++) {
            const float* p = &As[buf][(wm*32 + mt*16 + g)*GSK + 2*t];
            float2 x0 = *(const float2*)p;
            float2 x1 = *(const float2*)(p + 8*GSK);
            float2 x2 = *(const float2*)(p + 8);
            float2 x3 = *(const float2*)(p + 8*GSK + 8);
            split2(x0.x, x0.y, ah[mt][0], al[mt][0]);
            split2(x1.x, x1.y, ah[mt][1], al[mt][1]);
            split2(x2.x, x2.y, ah[mt][2], al[mt][2]);
            split2(x3.x, x3.y, ah[mt][3], al[mt][3]);
        }
        #pragma unroll
        for (int nt = 0; nt < 8; nt++) {
            int bi = (wn*64 + nt*8 + g)*BSP + t;
            unsigned bh[2], bl[2];
            bh[0] = sBh[buf][bi]; bh[1] = sBh[buf][bi + 4];
            bl[0] = sBl[buf][bi]; bl[1] = sBl[buf][bi + 4];
            #pragma unroll
            for (int mt = 0; mt < 2; mt++) {
                mma16(acc[mt][nt], ah[mt], bh);
                mma16(acc[mt][nt], ah[mt], bl);
                mma16(acc[mt][nt], al[mt], bh);
            }
        }

        if (ck < 15) {
            int nb = buf ^ 1;
            *(float4*)&As[nb][r*GSK + cb]     = a0;
            *(float4*)&As[nb][r*GSK + cb + 4] = a1;
            *(uint4*)&sBh[nb][r*BSP + h4] = nb0;
            *(uint4*)&sBl[nb][r*BSP + h4] = nb1;
            __syncthreads();
        }
    }

    if (act == 3) {
        #pragma unroll
        for (int mt = 0; mt < 2; mt++) {
            float p0 = 0.f, p1 = 0.f;
            #pragma unroll
            for (int nt = 0; nt < 8; nt++) {
                int col = n0 + wn*64 + nt*8 + t*2;
                float b0 = bias[col], b1 = bias[col+1];
                float w0 = w2[col],  w1 = w2[col+1];
                p0 += fmaxf(acc[mt][nt][0] + b0, 0.f)*w0 + fmaxf(acc[mt][nt][1] + b1, 0.f)*w1;
                p1 += fmaxf(acc[mt][nt][2] + b0, 0.f)*w0 + fmaxf(acc[mt][nt][3] + b1, 0.f)*w1;
            }
            p0 += __shfl_xor_sync(0xffffffffu, p0, 1);
            p0 += __shfl_xor_sync(0xffffffffu, p0, 2);
            p1 += __shfl_xor_sync(0xffffffffu, p1, 1);
            p1 += __shfl_xor_sync(0xffffffffu, p1, 2);
            if (t == 0) {
                int row = m0 + wm*32 + mt*16 + g;
                atomicAdd(&C[row], p0);
                atomicAdd(&C[row + 8], p1);
            }
        }
        return;
    }

    #pragma unroll
    for (int mt = 0; mt < 2; mt++) {
        int row0 = m0 + wm*32 + mt*16 + g;
        #pragma unroll
        for (int nt = 0; nt < 8; nt++) {
            int col = n0 + wn*64 + nt*8 + t*2;
            int coll = col & 255;
            float b0 = bias[col], b1 = bias[col+1];
            float v0 = acc[mt][nt][0] + b0;
            float v1 = acc[mt][nt][1] + b1;
            float v2 = acc[mt][nt][2] + b0;
            float v3 = acc[mt][nt][3] + b1;
            if (act == 1) {
                v0 = 1.f/(1.f+__expf(-v0)); v1 = 1.f/(1.f+__expf(-v1));
                v2 = 1.f/(1.f+__expf(-v2)); v3 = 1.f/(1.f+__expf(-v3));
            }
            *(float2*)&Cb[(size_t)row0*DM + coll]     = make_float2(v0, v1);
            *(float2*)&Cb[(size_t)(row0+8)*DM + coll] = make_float2(v2, v3);
        }
    }
}

// ---------------- flash attention (bf16x3 both stages, cp.async) ----------
#define QSP 36
#define KSS 72
#define VSS 68
#define SSS 68
#define SPP 36
#define ATT_WORDS (2*64*QSP + 64*KSS + 64*VSS + 64*SSS + 2*64*SPP + 3*64)
#define ATT_SMEM (ATT_WORDS*4)

__global__ __launch_bounds__(256, 2)
void attn_kernel(const float* __restrict__ Q, const float* __restrict__ Km,
                 const float* __restrict__ V, float* __restrict__ O)
{
    extern __shared__ float sm[];
    unsigned* Qph = (unsigned*)sm;
    unsigned* Qpl = Qph + 64*QSP;
    float* KV0 = (float*)(Qpl + 64*QSP);
    float* KV1 = KV0 + 64*KSS;
    float* Sh  = KV1 + 64*VSS;
    unsigned* Sph = (unsigned*)(Sh + 64*SSS);
    unsigned* Spl = Sph + 64*SPP;
    float* mrow = (float*)(Spl + 64*SPP);
    float* lrow = mrow + 64;
    float* crow = lrow + 64;

    unsigned kv0s = (unsigned)__cvta_generic_to_shared(KV0);
    unsigned kv1s = (unsigned)__cvta_generic_to_shared(KV1);

    int qb = blockIdx.x, h = blockIdx.y, b = blockIdx.z;
    int tid = threadIdx.x;
    int q0 = qb * 64;

    int w = tid >> 5, lane = tid & 31;
    int g = lane >> 2, t = lane & 3;
    int wq = w >> 1, wk = w & 1;
    int q0r = wq*16, kc0 = wk*32;

    const float* Kbase = Km + ((size_t)(b*NSEQ))*DM + h*64;
    const float* Vbase = V  + ((size_t)(b*NSEQ))*DM + h*64;

    for (int i = tid; i < 64*16; i += 256) {
        int q = i >> 4, d4 = (i & 15) * 4;
        float4 v = *(const float4*)&Q[((size_t)(b*NSEQ + q0 + q))*DM + h*64 + d4];
        unsigned h0, l0, h1, l1;
        split2(v.x*0.125f, v.y*0.125f, h0, l0);
        split2(v.z*0.125f, v.w*0.125f, h1, l1);
        int pi = q*QSP + (d4 >> 1);
        Qph[pi] = h0; Qph[pi+1] = h1;
        Qpl[pi] = l0; Qpl[pi+1] = l1;
    }
    if (tid < 64) { mrow[tid] = -1e30f; lrow[tid] = 0.f; }

    #pragma unroll
    for (int i = 0; i < 4; i++) {
        int idx = tid + i*256;
        int row = idx >> 4, d4 = (idx & 15) * 4;
        cpa16(kv0s + (row*KSS + d4)*4, Kbase + (size_t)row*DM + d4);
    }
    CP_COMMIT();

    float oacc[4][4] = {};

    #pragma unroll 1
    for (int kt = 0; kt < 16; kt++) {
        #pragma unroll
        for (int i = 0; i < 4; i++) {
            int idx = tid + i*256;
            int row = idx >> 4, d4 = (idx & 15) * 4;
            cpa16(kv1s + (row*VSS + d4)*4, Vbase + (size_t)(kt*64 + row)*DM + d4);
        }
        CP_COMMIT();
        CP_WAIT1();
        __syncthreads();

        {
            float sacc[4][4] = {};
            #pragma unroll
            for (int dk = 0; dk < 64; dk += 16) {
                int kp = dk >> 1;
                unsigned qa[4], ql[4];
                {
                    const unsigned* ph = &Qph[(q0r + g)*QSP + kp + t];
                    const unsigned* pl = &Qpl[(q0r + g)*QSP + kp + t];
                    qa[0] = ph[0]; qa[1] = ph[8*QSP]; qa[2] = ph[4]; qa[3] = ph[8*QSP + 4];
                    ql[0] = pl[0]; ql[1] = pl[8*QSP]; ql[2] = pl[4]; ql[3] = pl[8*QSP + 4];
                }
                #pragma unroll
                for (int nt = 0; nt < 4; nt++) {
                    const float* p = &KV0[(kc0 + nt*8 + g)*KSS + dk + 2*t];
                    float2 y0 = *(const float2*)p;
                    float2 y1 = *(const float2*)(p + 8);
                    unsigned bh[2], bl[2];
                    split2(y0.x, y0.y, bh[0], bl[0]);
                    split2(y1.x, y1.y, bh[1], bl[1]);
                    mma16(sacc[nt], qa, bh);
                    mma16(sacc[nt], qa, bl);
                    mma16(sacc[nt], ql, bh);
                }
            }
            #pragma unroll
            for (int nt = 0; nt < 4; nt++) {
                int col = kc0 + nt*8 + t*2;
                *(float2*)&Sh[(q0r + g)*SSS + col]     = make_float2(sacc[nt][0], sacc[nt][1]);
                *(float2*)&Sh[(q0r + g + 8)*SSS + col] = make_float2(sacc[nt][2], sacc[nt][3]);
            }
        }
        __syncthreads();

        {
            int q = tid >> 2, part = tid & 3;
            int j0 = part * 16;
            float mold = mrow[q];
            float mx = mold;
            const float* row = Sh + q*SSS + j0;
            float pv[16];
            #pragma unroll
            for (int j = 0; j < 16; j++) { pv[j] = row[j]; mx = fmaxf(mx, pv[j]); }
            mx = fmaxf(mx, __shfl_xor_sync(0xffffffffu, mx, 1));
            mx = fmaxf(mx, __shfl_xor_sync(0xffffffffu, mx, 2));
            float ssum = 0.f;
            #pragma unroll
            for (int j = 0; j < 16; j++) { pv[j] = __expf(pv[j] - mx); ssum += pv[j]; }
            unsigned* oh = Sph + q*SPP + part*8;
            unsigned* ol = Spl + q*SPP + part*8;
            #pragma unroll
            for (int jj = 0; jj < 8; jj++) {
                unsigned hp, lp;
                split2(pv[2*jj], pv[2*jj+1], hp, lp);
                oh[jj] = hp; ol[jj] = lp;
            }
            ssum += __shfl_xor_sync(0xffffffffu, ssum, 1);
            ssum += __shfl_xor_sync(0xffffffffu, ssum, 2);
            if (part == 0) {
                float corr = __expf(mold - mx);
                lrow[q] = lrow[q]*corr + ssum;
                mrow[q] = mx;
                crow[q] = corr;
            }
        }
        __syncthreads();
        CP_WAIT0();
        __syncthreads();

        if (kt < 15) {
            #pragma unroll
            for (int i = 0; i < 4; i++) {
                int idx = tid + i*256;
                int row = idx >> 4, d4 = (idx & 15) * 4;
                cpa16(kv0s + (row*KSS + d4)*4, Kbase + (size_t)((kt+1)*64 + row)*DM + d4);
            }
            CP_COMMIT();
        }

        {
            float c0 = crow[q0r + g];
            float c1 = crow[q0r + g + 8];
            #pragma unroll
            for (int nt = 0; nt < 4; nt++) {
                oacc[nt][0] *= c0; oacc[nt][1] *= c0;
                oacc[nt][2] *= c1; oacc[nt][3] *= c1;
            }
            #pragma unroll
            for (int kk = 0; kk < 64; kk += 16) {
                int kp = kk >> 1;
                unsigned pa[4], pl[4];
                {
                    const unsigned* ph = &Sph[(q0r + g)*SPP + kp + t];
                    const unsigned* pq = &Spl[(q0r + g)*SPP + kp + t];
                    pa[0] = ph[0]; pa[1] = ph[8*SPP]; pa[2] = ph[4]; pa[3] = ph[8*SPP + 4];
                    pl[0] = pq[0]; pl[1] = pq[8*SPP]; pl[2] = pq[4]; pl[3] = pq[8*SPP + 4];
                }
                #pragma unroll
                for (int nt = 0; nt < 4; nt++) {
                    int dcol = kc0 + nt*8 + g;
                    float v0 = KV1[(kk + 2*t)*VSS + dcol];
                    float v1 = KV1[(kk + 2*t + 1)*VSS + dcol];
                    float v2 = KV1[(kk + 2*t + 8)*VSS + dcol];
                    float v3 = KV1[(kk + 2*t + 9)*VSS + dcol];
                    unsigned vh[2], vl[2];
                    split2(v0, v1, vh[0], vl[0]);
                    split2(v2, v3, vh[1], vl[1]);
                    mma16(oacc[nt], pa, vh);
                    mma16(oacc[nt], pa, vl);
                    mma16(oacc[nt], pl, vh);
                }
            }
        }
        __syncthreads();
    }

    float inv0 = 1.f / lrow[q0r + g];
    float inv1 = 1.f / lrow[q0r + g + 8];
    #pragma unroll
    for (int nt = 0; nt < 4; nt++) {
        int col = kc0 + nt*8 + t*2;
        *(float2*)&O[((size_t)(b*NSEQ + q0 + q0r + g))*DM + h*64 + col] =
            make_float2(oacc[nt][0]*inv0, oacc[nt][1]*inv0);
        *(float2*)&O[((size_t)(b*NSEQ + q0 + q0r + g + 8))*DM + h*64 + col] =
            make_float2(oacc[nt][2]*inv1, oacc[nt][3]*inv1);
    }
}

// ---------------- out init ----------------
__global__ void init_out_kernel(float* __restrict__ out, const float* __restrict__ b2)
{
    int i = blockIdx.x*256 + threadIdx.x;
    out[i] = b2[0];
}

// ---------------- host launch ----------------
extern "C" void kernel_launch(void* const* d_in, const int* in_sizes, int n_in,
                              void* d_out, int out_size)
{
    const float* sparse_coords = (const float*)d_in[0];
    const float* sparse_values = (const float*)d_in[1];
    const float* query_coords  = (const float*)d_in[2];
    const float* t_in          = (const float*)d_in[3];
    const float* noise         = (const float*)d_in[4];
    const float* B_f           = (const float*)d_in[5];
    const float* Wq_in         = (const float*)d_in[6];
    const float* bq_in         = (const float*)d_in[7];
    const float* Wi_in         = (const float*)d_in[8];
    const float* bi_in         = (const float*)d_in[9];
    const float* A_log         = (const float*)d_in[10];
    const float* Bw            = (const float*)d_in[11];
    const float* Cw            = (const float*)d_in[12];
    const float* Dp            = (const float*)d_in[13];
    const float* ln_g          = (const float*)d_in[14];
    const float* ln_b          = (const float*)d_in[15];
    const float* gate_w        = (const float*)d_in[16];
    const float* gate_b        = (const float*)d_in[17];
    const float* in_proj_w     = (const float*)d_in[18];
    const float* in_proj_b     = (const float*)d_in[19];
    const float* out_w         = (const float*)d_in[20];
    const float* out_b         = (const float*)d_in[21];
    const float* dec_w1        = (const float*)d_in[22];
    const float* dec_b1        = (const float*)d_in[23];
    const float* dec_w2        = (const float*)d_in[24];
    const float* dec_b2        = (const float*)d_in[25];
    float* out = (float*)d_out;

    float *p_seq, *p_xn, *p_gate, *p_bu, *p_hs, *p_qkv, *p_att, *p_wc, *p_bc;
    unsigned *p_wh, *p_wl;
    cudaGetSymbolAddress((void**)&p_seq, g_seq);
    cudaGetSymbolAddress((void**)&p_xn,  g_xn);
    cudaGetSymbolAddress((void**)&p_gate,g_gate);
    cudaGetSymbolAddress((void**)&p_bu,  g_bu);
    cudaGetSymbolAddress((void**)&p_hs,  g_hs);
    cudaGetSymbolAddress((void**)&p_qkv, g_qkv);
    cudaGetSymbolAddress((void**)&p_att, g_att);
    cudaGetSymbolAddress((void**)&p_wc,  g_wc);
    cudaGetSymbolAddress((void**)&p_bc,  g_bc);
    cudaGetSymbolAddress((void**)&p_wh,  g_wh);
    cudaGetSymbolAddress((void**)&p_wl,  g_wl);

    cudaFuncSetAttribute(attn_kernel, cudaFuncAttributeMaxDynamicSharedMemorySize, ATT_SMEM);

    int ntok_all = BATCH*NTOK;          // 32768
    int nq_all   = BATCH*NSEQ;          // 16384
    const int BIGR = 1 << 30;

    pack_kernel<<<(131072+255)/256, 256>>>(gate_w,    p_wh + OFF_GATE,   p_wl + OFF_GATE,   131072);
    pack_kernel<<<( 98304+255)/256, 256>>>(in_proj_w, p_wh + OFF_INPROJ, p_wl + OFF_INPROJ,  98304);
    comb_wb_kernel<<<DM, DM>>>(dec_w1, out_w, out_b, dec_b1, p_wc, p_bc);
    pack_kernel<<<(32768+255)/256, 256>>>(p_wc, p_wh + OFF_DEC, p_wl + OFF_DEC, 32768);

    embed_ln_bu_kernel<<<ntok_all, 256>>>(sparse_coords, sparse_values, query_coords, t_in,
                                          noise, B_f, Wq_in, bq_in, Wi_in, bi_in,
                                          ln_g, ln_b, Bw, p_seq, p_xn, p_bu);

    for (int l = 0; l < NLAYER; l++) {
        gemm_tc<<<dim3(2, ntok_all/128), 256>>>(p_xn,
                                                p_wh + OFF_GATE + l*32768, p_wl + OFF_GATE + l*32768,
                                                gate_b + l*DM, p_gate, nullptr,
                                                BIGR, 0, 0, 1);
        scan_kernel<<<BATCH*NSTATE, 32>>>(A_log + l*NSTATE, p_bu, p_hs);
        if (l < NLAYER-1) {
            ssm_ln_bu_kernel<<<ntok_all, 256>>>(Cw + l*DM*NSTATE, Dp + l*DM,
                                                p_xn, p_hs, p_gate, p_seq,
                                                ln_g + (l+1)*DM, ln_b + (l+1)*DM,
                                                Bw + (l+1)*NSTATE*DM,
                                                p_xn, p_bu);
        } else {
            ssm_out_kernel<<<ntok_all, 256>>>(Cw + l*DM*NSTATE, Dp + l*DM,
                                              p_xn, p_hs, p_gate, p_seq);
        }
    }

    // fused q|k|v GEMM: N=768, one launch (act=4 handles row map + segment out)
    gemm_tc<<<dim3(6, nq_all/128), 256>>>(p_seq, p_wh + OFF_INPROJ, p_wl + OFF_INPROJ,
                                          in_proj_b, p_qkv, nullptr,
                                          NSEQ, NTOK, 0, 4);

    attn_kernel<<<dim3(16, 4, BATCH), 256, ATT_SMEM>>>(p_qkv, p_qkv + SEGSZ, p_qkv + 2*SEGSZ, p_att);

    init_out_kernel<<<nq_all/256, 256>>>(out, dec_b2);
    gemm_tc<<<dim3(2, nq_all/128), 256>>>(p_att, p_wh + OFF_DEC, p_wl + OFF_DEC,
                                          p_bc, out, dec_w2, BIGR, 0, 0, 3);
}

// round 14
// speedup vs baseline: 1.0259x; 1.0259x over previous
#include <cuda_runtime.h>
#include <cstdint>

#define BATCH 16
#define NSEQ  1024
#define NTOK  2048
#define DM    256
#define NLAYER 4
#define NSTATE 8
#define NF    16
#define CIN   33
#define LN_EPS 1e-5f

// ---------------- scratch ----------------
__device__ float g_seq [BATCH*NTOK*DM];
__device__ float g_xn  [BATCH*NTOK*DM];
__device__ float g_gate[BATCH*NTOK*DM];
__device__ float g_bu  [BATCH*NSTATE*NTOK];
__device__ float g_hs  [BATCH*NSTATE*NTOK];
__device__ float g_q   [BATCH*NSEQ*DM];
__device__ float g_k   [BATCH*NSEQ*DM];
__device__ float g_v   [BATCH*NSEQ*DM];
__device__ float g_att [BATCH*NSEQ*DM];
__device__ float g_wc  [DM*DM];
__device__ float g_bc  [DM];
__device__ unsigned g_wh[294912];
__device__ unsigned g_wl[294912];

#define OFF_GATE   0
#define OFF_INPROJ 131072
#define OFF_DEC    262144

// ---------------- bf16 split helpers ----------------
__device__ __forceinline__ unsigned packbf(float x0, float x1) {
    unsigned r;
    asm("cvt.rn.bf16x2.f32 %0, %1, %2;" : "=r"(r) : "f"(x1), "f"(x0));
    return r;
}
__device__ __forceinline__ void split2(float x0, float x1, unsigned& h, unsigned& l) {
    h = packbf(x0, x1);
    float h0 = __uint_as_float(h << 16);
    float h1 = __uint_as_float(h & 0xFFFF0000u);
    l = packbf(x0 - h0, x1 - h1);
}
__device__ __forceinline__ void mma16(float (&d)[4], const unsigned* a, const unsigned* b) {
    asm volatile("mma.sync.aligned.m16n8k16.row.col.f32.bf16.bf16.f32 "
        "{%0,%1,%2,%3}, {%4,%5,%6,%7}, {%8,%9}, {%0,%1,%2,%3};"
        : "+f"(d[0]), "+f"(d[1]), "+f"(d[2]), "+f"(d[3])
        : "r"(a[0]), "r"(a[1]), "r"(a[2]), "r"(a[3]), "r"(b[0]), "r"(b[1]));
}
__device__ __forceinline__ void cpa16(unsigned s, const void* g) {
    asm volatile("cp.async.cg.shared.global [%0], [%1], 16;" :: "r"(s), "l"(g));
}
#define CP_COMMIT() asm volatile("cp.async.commit_group;")
#define CP_WAIT0()  asm volatile("cp.async.wait_group 0;")
#define CP_WAIT1()  asm volatile("cp.async.wait_group 1;")

// ---------------- weight pack ----------------
__global__ void pack_kernel(const float* __restrict__ src,
                            unsigned* __restrict__ dh, unsigned* __restrict__ dl,
                            int npairs)
{
    int i = blockIdx.x*256 + threadIdx.x;
    if (i < npairs) {
        float2 v = ((const float2*)src)[i];
        unsigned h, l; split2(v.x, v.y, h, l);
        dh[i] = h; dl[i] = l;
    }
}

// ---------------- combine out_w into dec_w1 (+ bias fold) ----------------
__global__ void comb_wb_kernel(const float* __restrict__ w1,
                               const float* __restrict__ ow,
                               const float* __restrict__ ob,
                               const float* __restrict__ b1,
                               float* __restrict__ wc,
                               float* __restrict__ bc)
{
    __shared__ float row[DM];
    __shared__ float red[8];
    int i = blockIdx.x, j = threadIdx.x;
    row[j] = w1[i*DM + j];
    __syncthreads();
    float s = 0.f;
    #pragma unroll 8
    for (int k = 0; k < DM; k++) s += row[k] * ow[k*DM + j];
    wc[i*DM + j] = s;

    float p = row[j] * ob[j];
    #pragma unroll
    for (int o = 16; o; o >>= 1) p += __shfl_xor_sync(0xffffffffu, p, o);
    if ((j & 31) == 0) red[j >> 5] = p;
    __syncthreads();
    if (j == 0) {
        float t = b1[i];
        #pragma unroll
        for (int k = 0; k < 8; k++) t += red[k];
        bc[i] = t;
    }
}

// ---------------- LN + Bu core ----------------
__device__ __forceinline__ void ln_bu_body(float x, int token, int tid,
                                           const float* __restrict__ lng,
                                           const float* __restrict__ lnb,
                                           const float* __restrict__ Bw,
                                           float* __restrict__ xn_out,
                                           float* __restrict__ bu_out,
                                           float* xs, float* part)
{
    int w = tid >> 5, lane = tid & 31;
    float s = x;
    #pragma unroll
    for (int o = 16; o; o >>= 1) s += __shfl_xor_sync(0xffffffffu, s, o);
    if (lane == 0) part[w] = s;
    __syncthreads();
    float mu = 0.f;
    #pragma unroll
    for (int i = 0; i < 8; i++) mu += part[i];
    mu *= (1.f/256.f);
    float dx = x - mu;
    float s2 = dx*dx;
    #pragma unroll
    for (int o = 16; o; o >>= 1) s2 += __shfl_xor_sync(0xffffffffu, s2, o);
    __syncthreads();
    if (lane == 0) part[8 + w] = s2;
    __syncthreads();
    float var = 0.f;
    #pragma unroll
    for (int i = 0; i < 8; i++) var += part[8 + i];
    var *= (1.f/256.f);

    float xn = dx * rsqrtf(var + LN_EPS) * lng[tid] + lnb[tid];
    xn_out[(size_t)token*DM + tid] = xn;
    xs[tid] = xn;
    __syncthreads();

    float bs = 0.f;
    #pragma unroll
    for (int i = 0; i < 8; i++) {
        int d = lane + i*32;
        bs += xs[d] * Bw[w*DM + d];
    }
    #pragma unroll
    for (int o = 16; o; o >>= 1) bs += __shfl_xor_sync(0xffffffffu, bs, o);
    if (lane == 0) {
        int b = token >> 11, n = token & 2047;
        bu_out[((size_t)(b*NSTATE + w))*NTOK + n] = bs;
    }
}

// ---------------- fused embed + LN + Bu ----------------
__global__ void embed_ln_bu_kernel(const float* __restrict__ sparse_coords,
                                   const float* __restrict__ sparse_values,
                                   const float* __restrict__ query_coords,
                                   const float* __restrict__ t_in,
                                   const float* __restrict__ noise,
                                   const float* __restrict__ B_f,
                                   const float* __restrict__ Wq, const float* __restrict__ bq,
                                   const float* __restrict__ Wi, const float* __restrict__ bi,
                                   const float* __restrict__ lng, const float* __restrict__ lnb,
                                   const float* __restrict__ Bw,
                                   float* __restrict__ seq,
                                   float* __restrict__ xn_out, float* __restrict__ bu_out)
{
    __shared__ float feat[CIN];
    __shared__ float xs[DM];
    __shared__ float part[16];
    int token = blockIdx.x;
    int b = token / NTOK;
    int n = token % NTOK;
    int tid = threadIdx.x;

    const float* W; const float* bias;
    float cx, cy, val;
    if (n < NSEQ) {
        cx = sparse_coords[(b*NSEQ + n)*2 + 0];
        cy = sparse_coords[(b*NSEQ + n)*2 + 1];
        val = sparse_values[b*NSEQ + n];
        W = Wi; bias = bi;
    } else {
        int m = n - NSEQ;
        cx = query_coords[(b*NSEQ + m)*2 + 0];
        cy = query_coords[(b*NSEQ + m)*2 + 1];
        val = noise[b*NSEQ + m];
        W = Wq; bias = bq;
    }
    if (tid < NF) {
        float proj = cx * B_f[tid] + cy * B_f[NF + tid];
        feat[tid]      = sinf(proj);
        feat[NF + tid] = cosf(proj);
    }
    if (tid == 0) feat[2*NF] = val;
    __syncthreads();

    int d = tid;
    float acc = bias[d];
    const float* wrow = W + d*CIN;
    #pragma unroll
    for (int k = 0; k < CIN; k++) acc += feat[k] * wrow[k];

    float tv = t_in[b];
    float e;
    if (d < 128) e = sinf(tv * expf((float)d * (-9.210340371976184f / 127.f)));
    else         e = cosf(tv * expf((float)(d-128) * (-9.210340371976184f / 127.f)));

    float x = acc + e;
    seq[(size_t)token*DM + d] = x;
    __syncthreads();
    ln_bu_body(x, token, tid, lng, lnb, Bw, xn_out, bu_out, xs, part);
}

// ---------------- fused: ssm_out(l) + ln_bu(l+1) ----------------
__global__ void ssm_ln_bu_kernel(const float* __restrict__ Cw, const float* __restrict__ Dp,
                                 const float* __restrict__ xn, const float* __restrict__ hs,
                                 const float* __restrict__ gate, float* __restrict__ seq,
                                 const float* __restrict__ lng2, const float* __restrict__ lnb2,
                                 const float* __restrict__ Bw2,
                                 float* __restrict__ xn_out, float* __restrict__ bu_out)
{
    __shared__ float xs[DM];
    __shared__ float part[16];
    __shared__ float hsl[NSTATE];
    int token = blockIdx.x;
    int tid = threadIdx.x;
    if (tid < NSTATE) {
        int b = token >> 11, n = token & 2047;
        hsl[tid] = hs[((size_t)(b*NSTATE + tid))*NTOK + n];
    }
    __syncthreads();
    size_t idx = (size_t)token*DM + tid;
    float xv = xn[idx];
    float o = Dp[tid] * xv;
    #pragma unroll
    for (int s = 0; s < NSTATE; s++) o += hsl[s] * Cw[tid*NSTATE + s];
    float x = seq[idx] + gate[idx] * o;
    seq[idx] = x;
    __syncthreads();
    ln_bu_body(x, token, tid, lng2, lnb2, Bw2, xn_out, bu_out, xs, part);
}

// ---------------- last-layer ssm_out ----------------
__global__ void ssm_out_kernel(const float* __restrict__ Cw, const float* __restrict__ Dp,
                               const float* __restrict__ xn, const float* __restrict__ hs,
                               const float* __restrict__ gate, float* __restrict__ seq)
{
    int token = blockIdx.x;
    int tid = threadIdx.x;
    __shared__ float hsl[NSTATE];
    if (tid < NSTATE) {
        int b = token >> 11, n = token & 2047;
        hsl[tid] = hs[((size_t)(b*NSTATE + tid))*NTOK + n];
    }
    __syncthreads();
    size_t idx = (size_t)token*DM + tid;
    float xv = xn[idx];
    float o = Dp[tid] * xv;
    #pragma unroll
    for (int s = 0; s < NSTATE; s++) o += hsl[s] * Cw[tid*NSTATE + s];
    seq[idx] += gate[idx] * o;
}

// ---------------- tensor-core GEMM (bf16x3, pre-packed B) ----------------
// act: 0=none 1=sigmoid(+fused scan in extra y-blocks) 3=relu+dot(w2)->atomicAdd
#define GSK 24
#define BSP 12
__global__ __launch_bounds__(256, 2)
void gemm_tc(const float* __restrict__ A,
             const unsigned* __restrict__ Wh, const unsigned* __restrict__ Wl,
             const float* __restrict__ bias, float* __restrict__ C,
             const float* __restrict__ w2,
             const float* __restrict__ A_log,
             const float* __restrict__ bu, float* __restrict__ hs,
             int rpb, int tstride, int rowoff, int act)
{
    __shared__ float As[2][128*GSK];
    __shared__ unsigned sBh[2][128*BSP];
    __shared__ unsigned sBl[2][128*BSP];
    __shared__ float sb[NTOK];

    int tid = threadIdx.x;

    // ---- fused scan blocks (gate launch only: blockIdx.y >= 256) ----
    if (blockIdx.y >= 256) {
        if (tid < 32) {
            int wi = (blockIdx.y - 256) * 2 + blockIdx.x;   // 0..127
            int lane = tid;
            int s = wi & 7;
            float Av = -fminf(fmaxf(expf(A_log[s]), 1e-8f), 10.f);
            float Abar = expf(Av * (1.f/2048.f));
            float p64  = expf(Av * (1.f/32.f));
            const float* bup = bu + (size_t)wi*NTOK;
            float* hsp = hs + (size_t)wi*NTOK;
            #pragma unroll
            for (int i = 0; i < 64; i++) sb[lane + i*32] = bup[lane + i*32];
            __syncwarp();
            int base = lane * 64;
            float loc = 0.f;
            #pragma unroll 8
            for (int i = 0; i < 64; i++) loc = Abar*loc + sb[base + i];
            float aa = p64, bb = loc;
            #pragma unroll
            for (int off = 1; off < 32; off <<= 1) {
                float pa = __shfl_up_sync(0xffffffffu, aa, off);
                float pb = __shfl_up_sync(0xffffffffu, bb, off);
                if (lane >= off) { bb = aa*pb + bb; aa = aa*pa; }
            }
            float hin = __shfl_up_sync(0xffffffffu, bb, 1);
            if (lane == 0) hin = 0.f;
            float h = hin;
            #pragma unroll 8
            for (int i = 0; i < 64; i++) {
                h = Abar*h + sb[base + i];
                sb[base + i] = h;
            }
            __syncwarp();
            #pragma unroll
            for (int i = 0; i < 64; i++) hsp[lane + i*32] = sb[lane + i*32];
        }
        return;
    }

    int m0 = blockIdx.y * 128, n0 = blockIdx.x * 128;

    int r  = tid >> 1;
    int cb = (tid & 1) * 8;
    int h4 = (tid & 1) * 4;
    int m = m0 + r;
    int tok = (m / rpb) * tstride + rowoff + (m % rpb);
    const float*    Aptr  = A  + (size_t)tok*DM + cb;
    const unsigned* Bptrh = Wh + (size_t)(n0 + r)*128 + h4;
    const unsigned* Bptrl = Wl + (size_t)(n0 + r)*128 + h4;

    int w = tid >> 5, lane = tid & 31;
    int g = lane >> 2, t = lane & 3;
    int wm = w >> 1, wn = w & 1;

    float acc[2][8][4] = {};

    {
        float4 a0 = *(const float4*)Aptr;
        float4 a1 = *(const float4*)(Aptr + 4);
        uint4  b0 = *(const uint4*)Bptrh;
        uint4  b1 = *(const uint4*)Bptrl;
        *(float4*)&As[0][r*GSK + cb]     = a0;
        *(float4*)&As[0][r*GSK + cb + 4] = a1;
        *(uint4*)&sBh[0][r*BSP + h4] = b0;
        *(uint4*)&sBl[0][r*BSP + h4] = b1;
    }
    __syncthreads();

    #pragma unroll 1
    for (int ck = 0; ck < 16; ck++) {
        int buf = ck & 1;
        float4 a0, a1; uint4 nb0, nb1;
        if (ck < 15) {
            a0  = *(const float4*)(Aptr + (ck+1)*16);
            a1  = *(const float4*)(Aptr + (ck+1)*16 + 4);
            nb0 = *(const uint4*)(Bptrh + (ck+1)*8);
            nb1 = *(const uint4*)(Bptrl + (ck+1)*8);
        }

        unsigned ah[2][4], al[2][4];
        #pragma unroll
        for (int mt = 0; mt < 2; mt++) {
            const float* p = &As[buf][(wm*32 + mt*16 + g)*GSK + 2*t];
            float2 x0 = *(const float2*)p;
            float2 x1 = *(const float2*)(p + 8*GSK);
            float2 x2 = *(const float2*)(p + 8);
            float2 x3 = *(const float2*)(p + 8*GSK + 8);
            split2(x0.x, x0.y, ah[mt][0], al[mt][0]);
            split2(x1.x, x1.y, ah[mt][1], al[mt][1]);
            split2(x2.x, x2.y, ah[mt][2], al[mt][2]);
            split2(x3.x, x3.y, ah[mt][3], al[mt][3]);
        }
        #pragma unroll
        for (int nt = 0; nt < 8; nt++) {
            int bi = (wn*64 + nt*8 + g)*BSP + t;
            unsigned bh[2], bl[2];
            bh[0] = sBh[buf][bi]; bh[1] = sBh[buf][bi + 4];
            bl[0] = sBl[buf][bi]; bl[1] = sBl[buf][bi + 4];
            #pragma unroll
            for (int mt = 0; mt < 2; mt++) {
                mma16(acc[mt][nt], ah[mt], bh);
                mma16(acc[mt][nt], ah[mt], bl);
                mma16(acc[mt][nt], al[mt], bh);
            }
        }

        if (ck < 15) {
            int nb = buf ^ 1;
            *(float4*)&As[nb][r*GSK + cb]     = a0;
            *(float4*)&As[nb][r*GSK + cb + 4] = a1;
            *(uint4*)&sBh[nb][r*BSP + h4] = nb0;
            *(uint4*)&sBl[nb][r*BSP + h4] = nb1;
            __syncthreads();
        }
    }

    if (act == 3) {
        #pragma unroll
        for (int mt = 0; mt < 2; mt++) {
            float p0 = 0.f, p1 = 0.f;
            #pragma unroll
            for (int nt = 0; nt < 8; nt++) {
                int col = n0 + wn*64 + nt*8 + t*2;
                float b0 = bias[col], b1 = bias[col+1];
                float w0 = w2[col],  w1 = w2[col+1];
                p0 += fmaxf(acc[mt][nt][0] + b0, 0.f)*w0 + fmaxf(acc[mt][nt][1] + b1, 0.f)*w1;
                p1 += fmaxf(acc[mt][nt][2] + b0, 0.f)*w0 + fmaxf(acc[mt][nt][3] + b1, 0.f)*w1;
            }
            p0 += __shfl_xor_sync(0xffffffffu, p0, 1);
            p0 += __shfl_xor_sync(0xffffffffu, p0, 2);
            p1 += __shfl_xor_sync(0xffffffffu, p1, 1);
            p1 += __shfl_xor_sync(0xffffffffu, p1, 2);
            if (t == 0) {
                int row = m0 + wm*32 + mt*16 + g;
                atomicAdd(&C[row], p0);
                atomicAdd(&C[row + 8], p1);
            }
        }
        return;
    }

    #pragma unroll
    for (int mt = 0; mt < 2; mt++) {
        int row0 = m0 + wm*32 + mt*16 + g;
        #pragma unroll
        for (int nt = 0; nt < 8; nt++) {
            int col = n0 + wn*64 + nt*8 + t*2;
            float b0 = bias[col], b1 = bias[col+1];
            float v0 = acc[mt][nt][0] + b0;
            float v1 = acc[mt][nt][1] + b1;
            float v2 = acc[mt][nt][2] + b0;
            float v3 = acc[mt][nt][3] + b1;
            if (act == 1) {
                v0 = 1.f/(1.f+__expf(-v0)); v1 = 1.f/(1.f+__expf(-v1));
                v2 = 1.f/(1.f+__expf(-v2)); v3 = 1.f/(1.f+__expf(-v3));
            }
            *(float2*)&C[(size_t)row0*DM + col]     = make_float2(v0, v1);
            *(float2*)&C[(size_t)(row0+8)*DM + col] = make_float2(v2, v3);
        }
    }
}

// ---------------- flash attention (bf16x3 both stages, cp.async) ----------
#define QSP 36
#define KSS 72
#define VSS 68
#define SSS 68
#define SPP 36
#define ATT_WORDS (2*64*QSP + 64*KSS + 64*VSS + 64*SSS + 2*64*SPP + 3*64)
#define ATT_SMEM (ATT_WORDS*4)

__global__ __launch_bounds__(256, 2)
void attn_kernel(const float* __restrict__ Q, const float* __restrict__ Km,
                 const float* __restrict__ V, float* __restrict__ O)
{
    extern __shared__ float sm[];
    unsigned* Qph = (unsigned*)sm;
    unsigned* Qpl = Qph + 64*QSP;
    float* KV0 = (float*)(Qpl + 64*QSP);
    float* KV1 = KV0 + 64*KSS;
    float* Sh  = KV1 + 64*VSS;
    unsigned* Sph = (unsigned*)(Sh + 64*SSS);
    unsigned* Spl = Sph + 64*SPP;
    float* mrow = (float*)(Spl + 64*SPP);
    float* lrow = mrow + 64;
    float* crow = lrow + 64;

    unsigned kv0s = (unsigned)__cvta_generic_to_shared(KV0);
    unsigned kv1s = (unsigned)__cvta_generic_to_shared(KV1);

    int qb = blockIdx.x, h = blockIdx.y, b = blockIdx.z;
    int tid = threadIdx.x;
    int q0 = qb * 64;

    int w = tid >> 5, lane = tid & 31;
    int g = lane >> 2, t = lane & 3;
    int wq = w >> 1, wk = w & 1;
    int q0r = wq*16, kc0 = wk*32;

    const float* Kbase = Km + ((size_t)(b*NSEQ))*DM + h*64;
    const float* Vbase = V  + ((size_t)(b*NSEQ))*DM + h*64;

    for (int i = tid; i < 64*16; i += 256) {
        int q = i >> 4, d4 = (i & 15) * 4;
        float4 v = *(const float4*)&Q[((size_t)(b*NSEQ + q0 + q))*DM + h*64 + d4];
        unsigned h0, l0, h1, l1;
        split2(v.x*0.125f, v.y*0.125f, h0, l0);
        split2(v.z*0.125f, v.w*0.125f, h1, l1);
        int pi = q*QSP + (d4 >> 1);
        Qph[pi] = h0; Qph[pi+1] = h1;
        Qpl[pi] = l0; Qpl[pi+1] = l1;
    }
    if (tid < 64) { mrow[tid] = -1e30f; lrow[tid] = 0.f; }

    #pragma unroll
    for (int i = 0; i < 4; i++) {
        int idx = tid + i*256;
        int row = idx >> 4, d4 = (idx & 15) * 4;
        cpa16(kv0s + (row*KSS + d4)*4, Kbase + (size_t)row*DM + d4);
    }
    CP_COMMIT();

    float oacc[4][4] = {};

    #pragma unroll 1
    for (int kt = 0; kt < 16; kt++) {
        #pragma unroll
        for (int i = 0; i < 4; i++) {
            int idx = tid + i*256;
            int row = idx >> 4, d4 = (idx & 15) * 4;
            cpa16(kv1s + (row*VSS + d4)*4, Vbase + (size_t)(kt*64 + row)*DM + d4);
        }
        CP_COMMIT();
        CP_WAIT1();
        __syncthreads();

        {
            float sacc[4][4] = {};
            #pragma unroll
            for (int dk = 0; dk < 64; dk += 16) {
                int kp = dk >> 1;
                unsigned qa[4], ql[4];
                {
                    const unsigned* ph = &Qph[(q0r + g)*QSP + kp + t];
                    const unsigned* pl = &Qpl[(q0r + g)*QSP + kp + t];
                    qa[0] = ph[0]; qa[1] = ph[8*QSP]; qa[2] = ph[4]; qa[3] = ph[8*QSP + 4];
                    ql[0] = pl[0]; ql[1] = pl[8*QSP]; ql[2] = pl[4]; ql[3] = pl[8*QSP + 4];
                }
                #pragma unroll
                for (int nt = 0; nt < 4; nt++) {
                    const float* p = &KV0[(kc0 + nt*8 + g)*KSS + dk + 2*t];
                    float2 y0 = *(const float2*)p;
                    float2 y1 = *(const float2*)(p + 8);
                    unsigned bh[2], bl[2];
                    split2(y0.x, y0.y, bh[0], bl[0]);
                    split2(y1.x, y1.y, bh[1], bl[1]);
                    mma16(sacc[nt], qa, bh);
                    mma16(sacc[nt], qa, bl);
                    mma16(sacc[nt], ql, bh);
                }
            }
            #pragma unroll
            for (int nt = 0; nt < 4; nt++) {
                int col = kc0 + nt*8 + t*2;
                *(float2*)&Sh[(q0r + g)*SSS + col]     = make_float2(sacc[nt][0], sacc[nt][1]);
                *(float2*)&Sh[(q0r + g + 8)*SSS + col] = make_float2(sacc[nt][2], sacc[nt][3]);
            }
        }
        __syncthreads();

        {
            int q = tid >> 2, part = tid & 3;
            int j0 = part * 16;
            float mold = mrow[q];
            float mx = mold;
            const float* row = Sh + q*SSS + j0;
            float pv[16];
            #pragma unroll
            for (int j = 0; j < 16; j++) { pv[j] = row[j]; mx = fmaxf(mx, pv[j]); }
            mx = fmaxf(mx, __shfl_xor_sync(0xffffffffu, mx, 1));
            mx = fmaxf(mx, __shfl_xor_sync(0xffffffffu, mx, 2));
            float ssum = 0.f;
            #pragma unroll
            for (int j = 0; j < 16; j++) { pv[j] = __expf(pv[j] - mx); ssum += pv[j]; }
            unsigned* oh = Sph + q*SPP + part*8;
            unsigned* ol = Spl + q*SPP + part*8;
            #pragma unroll
            for (int jj = 0; jj < 8; jj++) {
                unsigned hp, lp;
                split2(pv[2*jj], pv[2*jj+1], hp, lp);
                oh[jj] = hp; ol[jj] = lp;
            }
            ssum += __shfl_xor_sync(0xffffffffu, ssum, 1);
            ssum += __shfl_xor_sync(0xffffffffu, ssum, 2);
            if (part == 0) {
                float corr = __expf(mold - mx);
                lrow[q] = lrow[q]*corr + ssum;
                mrow[q] = mx;
                crow[q] = corr;
            }
        }
        __syncthreads();
        CP_WAIT0();
        __syncthreads();

        if (kt < 15) {
            #pragma unroll
            for (int i = 0; i < 4; i++) {
                int idx = tid + i*256;
                int row = idx >> 4, d4 = (idx & 15) * 4;
                cpa16(kv0s + (row*KSS + d4)*4, Kbase + (size_t)((kt+1)*64 + row)*DM + d4);
            }
            CP_COMMIT();
        }

        {
            float c0 = crow[q0r + g];
            float c1 = crow[q0r + g + 8];
            #pragma unroll
            for (int nt = 0; nt < 4; nt++) {
                oacc[nt][0] *= c0; oacc[nt][1] *= c0;
                oacc[nt][2] *= c1; oacc[nt][3] *= c1;
            }
            #pragma unroll
            for (int kk = 0; kk < 64; kk += 16) {
                int kp = kk >> 1;
                unsigned pa[4], pl[4];
                {
                    const unsigned* ph = &Sph[(q0r + g)*SPP + kp + t];
                    const unsigned* pq = &Spl[(q0r + g)*SPP + kp + t];
                    pa[0] = ph[0]; pa[1] = ph[8*SPP]; pa[2] = ph[4]; pa[3] = ph[8*SPP + 4];
                    pl[0] = pq[0]; pl[1] = pq[8*SPP]; pl[2] = pq[4]; pl[3] = pq[8*SPP + 4];
                }
                #pragma unroll
                for (int nt = 0; nt < 4; nt++) {
                    int dcol = kc0 + nt*8 + g;
                    float v0 = KV1[(kk + 2*t)*VSS + dcol];
                    float v1 = KV1[(kk + 2*t + 1)*VSS + dcol];
                    float v2 = KV1[(kk + 2*t + 8)*VSS + dcol];
                    float v3 = KV1[(kk + 2*t + 9)*VSS + dcol];
                    unsigned vh[2], vl[2];
                    split2(v0, v1, vh[0], vl[0]);
                    split2(v2, v3, vh[1], vl[1]);
                    mma16(oacc[nt], pa, vh);
                    mma16(oacc[nt], pa, vl);
                    mma16(oacc[nt], pl, vh);
                }
            }
        }
        __syncthreads();
    }

    float inv0 = 1.f / lrow[q0r + g];
    float inv1 = 1.f / lrow[q0r + g + 8];
    #pragma unroll
    for (int nt = 0; nt < 4; nt++) {
        int col = kc0 + nt*8 + t*2;
        *(float2*)&O[((size_t)(b*NSEQ + q0 + q0r + g))*DM + h*64 + col] =
            make_float2(oacc[nt][0]*inv0, oacc[nt][1]*inv0);
        *(float2*)&O[((size_t)(b*NSEQ + q0 + q0r + g + 8))*DM + h*64 + col] =
            make_float2(oacc[nt][2]*inv1, oacc[nt][3]*inv1);
    }
}

// ---------------- out init ----------------
__global__ void init_out_kernel(float* __restrict__ out, const float* __restrict__ b2)
{
    int i = blockIdx.x*256 + threadIdx.x;
    out[i] = b2[0];
}

// ---------------- host launch ----------------
extern "C" void kernel_launch(void* const* d_in, const int* in_sizes, int n_in,
                              void* d_out, int out_size)
{
    const float* sparse_coords = (const float*)d_in[0];
    const float* sparse_values = (const float*)d_in[1];
    const float* query_coords  = (const float*)d_in[2];
    const float* t_in          = (const float*)d_in[3];
    const float* noise         = (const float*)d_in[4];
    const float* B_f           = (const float*)d_in[5];
    const float* Wq_in         = (const float*)d_in[6];
    const float* bq_in         = (const float*)d_in[7];
    const float* Wi_in         = (const float*)d_in[8];
    const float* bi_in         = (const float*)d_in[9];
    const float* A_log         = (const float*)d_in[10];
    const float* Bw            = (const float*)d_in[11];
    const float* Cw            = (const float*)d_in[12];
    const float* Dp            = (const float*)d_in[13];
    const float* ln_g          = (const float*)d_in[14];
    const float* ln_b          = (const float*)d_in[15];
    const float* gate_w        = (const float*)d_in[16];
    const float* gate_b        = (const float*)d_in[17];
    const float* in_proj_w     = (const float*)d_in[18];
    const float* in_proj_b     = (const float*)d_in[19];
    const float* out_w         = (const float*)d_in[20];
    const float* out_b         = (const float*)d_in[21];
    const float* dec_w1        = (const float*)d_in[22];
    const float* dec_b1        = (const float*)d_in[23];
    const float* dec_w2        = (const float*)d_in[24];
    const float* dec_b2        = (const float*)d_in[25];
    float* out = (float*)d_out;

    float *p_seq, *p_xn, *p_gate, *p_bu, *p_hs, *p_q, *p_k, *p_v, *p_att, *p_wc, *p_bc;
    unsigned *p_wh, *p_wl;
    cudaGetSymbolAddress((void**)&p_seq, g_seq);
    cudaGetSymbolAddress((void**)&p_xn,  g_xn);
    cudaGetSymbolAddress((void**)&p_gate,g_gate);
    cudaGetSymbolAddress((void**)&p_bu,  g_bu);
    cudaGetSymbolAddress((void**)&p_hs,  g_hs);
    cudaGetSymbolAddress((void**)&p_q,   g_q);
    cudaGetSymbolAddress((void**)&p_k,   g_k);
    cudaGetSymbolAddress((void**)&p_v,   g_v);
    cudaGetSymbolAddress((void**)&p_att, g_att);
    cudaGetSymbolAddress((void**)&p_wc,  g_wc);
    cudaGetSymbolAddress((void**)&p_bc,  g_bc);
    cudaGetSymbolAddress((void**)&p_wh,  g_wh);
    cudaGetSymbolAddress((void**)&p_wl,  g_wl);

    cudaFuncSetAttribute(attn_kernel, cudaFuncAttributeMaxDynamicSharedMemorySize, ATT_SMEM);

    int ntok_all = BATCH*NTOK;          // 32768
    int nq_all   = BATCH*NSEQ;          // 16384
    const int BIGR = 1 << 30;

    pack_kernel<<<(131072+255)/256, 256>>>(gate_w,    p_wh + OFF_GATE,   p_wl + OFF_GATE,   131072);
    pack_kernel<<<( 98304+255)/256, 256>>>(in_proj_w, p_wh + OFF_INPROJ, p_wl + OFF_INPROJ,  98304);
    comb_wb_kernel<<<DM, DM>>>(dec_w1, out_w, out_b, dec_b1, p_wc, p_bc);
    pack_kernel<<<(32768+255)/256, 256>>>(p_wc, p_wh + OFF_DEC, p_wl + OFF_DEC, 32768);

    embed_ln_bu_kernel<<<ntok_all, 256>>>(sparse_coords, sparse_values, query_coords, t_in,
                                          noise, B_f, Wq_in, bq_in, Wi_in, bi_in,
                                          ln_g, ln_b, Bw, p_seq, p_xn, p_bu);

    for (int l = 0; l < NLAYER; l++) {
        // gate GEMM + fused scan (extra 64 y-blocks)
        gemm_tc<<<dim3(2, ntok_all/128 + 64), 256>>>(p_xn,
                                                p_wh + OFF_GATE + l*32768, p_wl + OFF_GATE + l*32768,
                                                gate_b + l*DM, p_gate, nullptr,
                                                A_log + l*NSTATE, p_bu, p_hs,
                                                BIGR, 0, 0, 1);
        if (l < NLAYER-1) {
            ssm_ln_bu_kernel<<<ntok_all, 256>>>(Cw + l*DM*NSTATE, Dp + l*DM,
                                                p_xn, p_hs, p_gate, p_seq,
                                                ln_g + (l+1)*DM, ln_b + (l+1)*DM,
                                                Bw + (l+1)*NSTATE*DM,
                                                p_xn, p_bu);
        } else {
            ssm_out_kernel<<<ntok_all, 256>>>(Cw + l*DM*NSTATE, Dp + l*DM,
                                              p_xn, p_hs, p_gate, p_seq);
        }
    }

    gemm_tc<<<dim3(2, nq_all/128), 256>>>(p_seq, p_wh + OFF_INPROJ,         p_wl + OFF_INPROJ,
                                          in_proj_b, p_q, nullptr, nullptr, nullptr, nullptr,
                                          NSEQ, NTOK, NSEQ, 0);
    gemm_tc<<<dim3(2, nq_all/128), 256>>>(p_seq, p_wh + OFF_INPROJ + 32768, p_wl + OFF_INPROJ + 32768,
                                          in_proj_b + DM, p_k, nullptr, nullptr, nullptr, nullptr,
                                          NSEQ, NTOK, 0, 0);
    gemm_tc<<<dim3(2, nq_all/128), 256>>>(p_seq, p_wh + OFF_INPROJ + 65536, p_wl + OFF_INPROJ + 65536,
                                          in_proj_b + 2*DM, p_v, nullptr, nullptr, nullptr, nullptr,
                                          NSEQ, NTOK, 0, 0);

    attn_kernel<<<dim3(16, 4, BATCH), 256, ATT_SMEM>>>(p_q, p_k, p_v, p_att);

    init_out_kernel<<<nq_all/256, 256>>>(out, dec_b2);
    gemm_tc<<<dim3(2, nq_all/128), 256>>>(p_att, p_wh + OFF_DEC, p_wl + OFF_DEC,
                                          p_bc, out, dec_w2, nullptr, nullptr, nullptr,
                                          BIGR, 0, 0, 3);
}

// round 15
// speedup vs baseline: 1.0272x; 1.0012x over previous
#include <cuda_runtime.h>
#include <cstdint>

#define BATCH 16
#define NSEQ  1024
#define NTOK  2048
#define DM    256
#define NLAYER 4
#define NSTATE 8
#define NF    16
#define CIN   33
#define LN_EPS 1e-5f
#define KVLD  512

// ---------------- scratch ----------------
__device__ float g_seq [BATCH*NTOK*DM];
__device__ float g_xn  [BATCH*NTOK*DM];
__device__ float g_gate[BATCH*NTOK*DM];
__device__ float g_bu  [BATCH*NSTATE*NTOK];
__device__ float g_hs  [BATCH*NSTATE*NTOK];
__device__ float g_q   [BATCH*NSEQ*DM];
__device__ float g_kv  [BATCH*NSEQ*KVLD];
__device__ float g_att [BATCH*NSEQ*DM];
__device__ float g_wc  [DM*DM];
__device__ float g_bc  [DM];
__device__ unsigned g_wh[294912];
__device__ unsigned g_wl[294912];

#define OFF_GATE   0
#define OFF_INPROJ 131072
#define OFF_DEC    262144

// ---------------- bf16 split helpers ----------------
__device__ __forceinline__ unsigned packbf(float x0, float x1) {
    unsigned r;
    asm("cvt.rn.bf16x2.f32 %0, %1, %2;" : "=r"(r) : "f"(x1), "f"(x0));
    return r;
}
__device__ __forceinline__ void split2(float x0, float x1, unsigned& h, unsigned& l) {
    h = packbf(x0, x1);
    float h0 = __uint_as_float(h << 16);
    float h1 = __uint_as_float(h & 0xFFFF0000u);
    l = packbf(x0 - h0, x1 - h1);
}
__device__ __forceinline__ void mma16(float (&d)[4], const unsigned* a, const unsigned* b) {
    asm volatile("mma.sync.aligned.m16n8k16.row.col.f32.bf16.bf16.f32 "
        "{%0,%1,%2,%3}, {%4,%5,%6,%7}, {%8,%9}, {%0,%1,%2,%3};"
        : "+f"(d[0]), "+f"(d[1]), "+f"(d[2]), "+f"(d[3])
        : "r"(a[0]), "r"(a[1]), "r"(a[2]), "r"(a[3]), "r"(b[0]), "r"(b[1]));
}
__device__ __forceinline__ void cpa16(unsigned s, const void* g) {
    asm volatile("cp.async.cg.shared.global [%0], [%1], 16;" :: "r"(s), "l"(g));
}
#define CP_COMMIT() asm volatile("cp.async.commit_group;")
#define CP_WAIT0()  asm volatile("cp.async.wait_group 0;")
#define CP_WAIT1()  asm volatile("cp.async.wait_group 1;")

// ---------------- weight pack ----------------
__global__ void pack_kernel(const float* __restrict__ src,
                            unsigned* __restrict__ dh, unsigned* __restrict__ dl,
                            int npairs)
{
    int i = blockIdx.x*256 + threadIdx.x;
    if (i < npairs) {
        float2 v = ((const float2*)src)[i];
        unsigned h, l; split2(v.x, v.y, h, l);
        dh[i] = h; dl[i] = l;
    }
}

// ---------------- combine out_w into dec_w1 (+ bias fold) ----------------
__global__ void comb_wb_kernel(const float* __restrict__ w1,
                               const float* __restrict__ ow,
                               const float* __restrict__ ob,
                               const float* __restrict__ b1,
                               float* __restrict__ wc,
                               float* __restrict__ bc)
{
    __shared__ float row[DM];
    __shared__ float red[8];
    int i = blockIdx.x, j = threadIdx.x;
    row[j] = w1[i*DM + j];
    __syncthreads();
    float s = 0.f;
    #pragma unroll 8
    for (int k = 0; k < DM; k++) s += row[k] * ow[k*DM + j];
    wc[i*DM + j] = s;

    float p = row[j] * ob[j];
    #pragma unroll
    for (int o = 16; o; o >>= 1) p += __shfl_xor_sync(0xffffffffu, p, o);
    if ((j & 31) == 0) red[j >> 5] = p;
    __syncthreads();
    if (j == 0) {
        float t = b1[i];
        #pragma unroll
        for (int k = 0; k < 8; k++) t += red[k];
        bc[i] = t;
    }
}

// ---------------- LN + Bu core ----------------
__device__ __forceinline__ void ln_bu_body(float x, int token, int tid,
                                           const float* __restrict__ lng,
                                           const float* __restrict__ lnb,
                                           const float* __restrict__ Bw,
                                           float* __restrict__ xn_out,
                                           float* __restrict__ bu_out,
                                           float* xs, float* part)
{
    int w = tid >> 5, lane = tid & 31;
    float s = x;
    #pragma unroll
    for (int o = 16; o; o >>= 1) s += __shfl_xor_sync(0xffffffffu, s, o);
    if (lane == 0) part[w] = s;
    __syncthreads();
    float mu = 0.f;
    #pragma unroll
    for (int i = 0; i < 8; i++) mu += part[i];
    mu *= (1.f/256.f);
    float dx = x - mu;
    float s2 = dx*dx;
    #pragma unroll
    for (int o = 16; o; o >>= 1) s2 += __shfl_xor_sync(0xffffffffu, s2, o);
    __syncthreads();
    if (lane == 0) part[8 + w] = s2;
    __syncthreads();
    float var = 0.f;
    #pragma unroll
    for (int i = 0; i < 8; i++) var += part[8 + i];
    var *= (1.f/256.f);

    float xn = dx * rsqrtf(var + LN_EPS) * lng[tid] + lnb[tid];
    xn_out[(size_t)token*DM + tid] = xn;
    xs[tid] = xn;
    __syncthreads();

    float bs = 0.f;
    #pragma unroll
    for (int i = 0; i < 8; i++) {
        int d = lane + i*32;
        bs += xs[d] * Bw[w*DM + d];
    }
    #pragma unroll
    for (int o = 16; o; o >>= 1) bs += __shfl_xor_sync(0xffffffffu, bs, o);
    if (lane == 0) {
        int b = token >> 11, n = token & 2047;
        bu_out[((size_t)(b*NSTATE + w))*NTOK + n] = bs;
    }
}

// ---------------- fused embed + LN + Bu ----------------
__global__ void embed_ln_bu_kernel(const float* __restrict__ sparse_coords,
                                   const float* __restrict__ sparse_values,
                                   const float* __restrict__ query_coords,
                                   const float* __restrict__ t_in,
                                   const float* __restrict__ noise,
                                   const float* __restrict__ B_f,
                                   const float* __restrict__ Wq, const float* __restrict__ bq,
                                   const float* __restrict__ Wi, const float* __restrict__ bi,
                                   const float* __restrict__ lng, const float* __restrict__ lnb,
                                   const float* __restrict__ Bw,
                                   float* __restrict__ seq,
                                   float* __restrict__ xn_out, float* __restrict__ bu_out)
{
    __shared__ float feat[CIN];
    __shared__ float xs[DM];
    __shared__ float part[16];
    int token = blockIdx.x;
    int b = token / NTOK;
    int n = token % NTOK;
    int tid = threadIdx.x;

    const float* W; const float* bias;
    float cx, cy, val;
    if (n < NSEQ) {
        cx = sparse_coords[(b*NSEQ + n)*2 + 0];
        cy = sparse_coords[(b*NSEQ + n)*2 + 1];
        val = sparse_values[b*NSEQ + n];
        W = Wi; bias = bi;
    } else {
        int m = n - NSEQ;
        cx = query_coords[(b*NSEQ + m)*2 + 0];
        cy = query_coords[(b*NSEQ + m)*2 + 1];
        val = noise[b*NSEQ + m];
        W = Wq; bias = bq;
    }
    if (tid < NF) {
        float proj = cx * B_f[tid] + cy * B_f[NF + tid];
        feat[tid]      = sinf(proj);
        feat[NF + tid] = cosf(proj);
    }
    if (tid == 0) feat[2*NF] = val;
    __syncthreads();

    int d = tid;
    float acc = bias[d];
    const float* wrow = W + d*CIN;
    #pragma unroll
    for (int k = 0; k < CIN; k++) acc += feat[k] * wrow[k];

    float tv = t_in[b];
    float e;
    if (d < 128) e = sinf(tv * expf((float)d * (-9.210340371976184f / 127.f)));
    else         e = cosf(tv * expf((float)(d-128) * (-9.210340371976184f / 127.f)));

    float x = acc + e;
    seq[(size_t)token*DM + d] = x;
    __syncthreads();
    ln_bu_body(x, token, tid, lng, lnb, Bw, xn_out, bu_out, xs, part);
}

// ---------------- fused: ssm_out(l) + ln_bu(l+1) ----------------
__global__ void ssm_ln_bu_kernel(const float* __restrict__ Cw, const float* __restrict__ Dp,
                                 const float* __restrict__ xn, const float* __restrict__ hs,
                                 const float* __restrict__ gate, float* __restrict__ seq,
                                 const float* __restrict__ lng2, const float* __restrict__ lnb2,
                                 const float* __restrict__ Bw2,
                                 float* __restrict__ xn_out, float* __restrict__ bu_out)
{
    __shared__ float xs[DM];
    __shared__ float part[16];
    __shared__ float hsl[NSTATE];
    int token = blockIdx.x;
    int tid = threadIdx.x;
    if (tid < NSTATE) {
        int b = token >> 11, n = token & 2047;
        hsl[tid] = hs[((size_t)(b*NSTATE + tid))*NTOK + n];
    }
    __syncthreads();
    size_t idx = (size_t)token*DM + tid;
    float xv = xn[idx];
    float o = Dp[tid] * xv;
    #pragma unroll
    for (int s = 0; s < NSTATE; s++) o += hsl[s] * Cw[tid*NSTATE + s];
    float x = seq[idx] + gate[idx] * o;
    seq[idx] = x;
    __syncthreads();
    ln_bu_body(x, token, tid, lng2, lnb2, Bw2, xn_out, bu_out, xs, part);
}

// ---------------- last-layer ssm_out ----------------
__global__ void ssm_out_kernel(const float* __restrict__ Cw, const float* __restrict__ Dp,
                               const float* __restrict__ xn, const float* __restrict__ hs,
                               const float* __restrict__ gate, float* __restrict__ seq)
{
    int token = blockIdx.x;
    int tid = threadIdx.x;
    __shared__ float hsl[NSTATE];
    if (tid < NSTATE) {
        int b = token >> 11, n = token & 2047;
        hsl[tid] = hs[((size_t)(b*NSTATE + tid))*NTOK + n];
    }
    __syncthreads();
    size_t idx = (size_t)token*DM + tid;
    float xv = xn[idx];
    float o = Dp[tid] * xv;
    #pragma unroll
    for (int s = 0; s < NSTATE; s++) o += hsl[s] * Cw[tid*NSTATE + s];
    seq[idx] += gate[idx] * o;
}

// ---------------- tensor-core GEMM (bf16x3, pre-packed B) ----------------
// act: 0=none 1=sigmoid(+fused scan in extra y-blocks) 3=relu+dot(w2)->atomicAdd
#define GSK 24
#define BSP 12
__global__ __launch_bounds__(256, 2)
void gemm_tc(const float* __restrict__ A,
             const unsigned* __restrict__ Wh, const unsigned* __restrict__ Wl,
             const float* __restrict__ bias, float* __restrict__ C,
             const float* __restrict__ w2,
             const float* __restrict__ A_log,
             const float* __restrict__ bu, float* __restrict__ hs,
             int rpb, int tstride, int rowoff, int ldc, int act)
{
    __shared__ float As[2][128*GSK];
    __shared__ unsigned sBh[2][128*BSP];
    __shared__ unsigned sBl[2][128*BSP];
    __shared__ float sb[NTOK];

    int tid = threadIdx.x;

    // ---- fused scan blocks (gate launch only: blockIdx.y >= 256) ----
    if (blockIdx.y >= 256) {
        if (tid < 32) {
            int wi = (blockIdx.y - 256) * 2 + blockIdx.x;   // 0..127
            int lane = tid;
            int s = wi & 7;
            float Av = -fminf(fmaxf(expf(A_log[s]), 1e-8f), 10.f);
            float Abar = expf(Av * (1.f/2048.f));
            float p64  = expf(Av * (1.f/32.f));
            const float* bup = bu + (size_t)wi*NTOK;
            float* hsp = hs + (size_t)wi*NTOK;
            #pragma unroll
            for (int i = 0; i < 64; i++) sb[lane + i*32] = bup[lane + i*32];
            __syncwarp();
            int base = lane * 64;
            float loc = 0.f;
            #pragma unroll 8
            for (int i = 0; i < 64; i++) loc = Abar*loc + sb[base + i];
            float aa = p64, bb = loc;
            #pragma unroll
            for (int off = 1; off < 32; off <<= 1) {
                float pa = __shfl_up_sync(0xffffffffu, aa, off);
                float pb = __shfl_up_sync(0xffffffffu, bb, off);
                if (lane >= off) { bb = aa*pb + bb; aa = aa*pa; }
            }
            float hin = __shfl_up_sync(0xffffffffu, bb, 1);
            if (lane == 0) hin = 0.f;
            float h = hin;
            #pragma unroll 8
            for (int i = 0; i < 64; i++) {
                h = Abar*h + sb[base + i];
                sb[base + i] = h;
            }
            __syncwarp();
            #pragma unroll
            for (int i = 0; i < 64; i++) hsp[lane + i*32] = sb[lane + i*32];
        }
        return;
    }

    int m0 = blockIdx.y * 128, n0 = blockIdx.x * 128;

    int r  = tid >> 1;
    int cb = (tid & 1) * 8;
    int h4 = (tid & 1) * 4;
    int m = m0 + r;
    int tok = (m / rpb) * tstride + rowoff + (m % rpb);
    const float*    Aptr  = A  + (size_t)tok*DM + cb;
    const unsigned* Bptrh = Wh + (size_t)(n0 + r)*128 + h4;
    const unsigned* Bptrl = Wl + (size_t)(n0 + r)*128 + h4;

    int w = tid >> 5, lane = tid & 31;
    int g = lane >> 2, t = lane & 3;
    int wm = w >> 1, wn = w & 1;

    float acc[2][8][4] = {};

    {
        float4 a0 = *(const float4*)Aptr;
        float4 a1 = *(const float4*)(Aptr + 4);
        uint4  b0 = *(const uint4*)Bptrh;
        uint4  b1 = *(const uint4*)Bptrl;
        *(float4*)&As[0][r*GSK + cb]     = a0;
        *(float4*)&As[0][r*GSK + cb + 4] = a1;
        *(uint4*)&sBh[0][r*BSP + h4] = b0;
        *(uint4*)&sBl[0][r*BSP + h4] = b1;
    }
    __syncthreads();

    #pragma unroll 1
    for (int ck = 0; ck < 16; ck++) {
        int buf = ck & 1;
        float4 a0, a1; uint4 nb0, nb1;
        if (ck < 15) {
            a0  = *(const float4*)(Aptr + (ck+1)*16);
            a1  = *(const float4*)(Aptr + (ck+1)*16 + 4);
            nb0 = *(const uint4*)(Bptrh + (ck+1)*8);
            nb1 = *(const uint4*)(Bptrl + (ck+1)*8);
        }

        unsigned ah[2][4], al[2][4];
        #pragma unroll
        for (int mt = 0; mt < 2; mt++) {
            const float* p = &As[buf][(wm*32 + mt*16 + g)*GSK + 2*t];
            float2 x0 = *(const float2*)p;
            float2 x1 = *(const float2*)(p + 8*GSK);
            float2 x2 = *(const float2*)(p + 8);
            float2 x3 = *(const float2*)(p + 8*GSK + 8);
            split2(x0.x, x0.y, ah[mt][0], al[mt][0]);
            split2(x1.x, x1.y, ah[mt][1], al[mt][1]);
            split2(x2.x, x2.y, ah[mt][2], al[mt][2]);
            split2(x3.x, x3.y, ah[mt][3], al[mt][3]);
        }
        #pragma unroll
        for (int nt = 0; nt < 8; nt++) {
            int bi = (wn*64 + nt*8 + g)*BSP + t;
            unsigned bh[2], bl[2];
            bh[0] = sBh[buf][bi]; bh[1] = sBh[buf][bi + 4];
            bl[0] = sBl[buf][bi]; bl[1] = sBl[buf][bi + 4];
            #pragma unroll
            for (int mt = 0; mt < 2; mt++) {
                mma16(acc[mt][nt], ah[mt], bh);
                mma16(acc[mt][nt], ah[mt], bl);
                mma16(acc[mt][nt], al[mt], bh);
            }
        }

        if (ck < 15) {
            int nb = buf ^ 1;
            *(float4*)&As[nb][r*GSK + cb]     = a0;
            *(float4*)&As[nb][r*GSK + cb + 4] = a1;
            *(uint4*)&sBh[nb][r*BSP + h4] = nb0;
            *(uint4*)&sBl[nb][r*BSP + h4] = nb1;
            __syncthreads();
        }
    }

    if (act == 3) {
        #pragma unroll
        for (int mt = 0; mt < 2; mt++) {
            float p0 = 0.f, p1 = 0.f;
            #pragma unroll
            for (int nt = 0; nt < 8; nt++) {
                int col = n0 + wn*64 + nt*8 + t*2;
                float b0 = bias[col], b1 = bias[col+1];
                float w0 = w2[col],  w1 = w2[col+1];
                p0 += fmaxf(acc[mt][nt][0] + b0, 0.f)*w0 + fmaxf(acc[mt][nt][1] + b1, 0.f)*w1;
                p1 += fmaxf(acc[mt][nt][2] + b0, 0.f)*w0 + fmaxf(acc[mt][nt][3] + b1, 0.f)*w1;
            }
            p0 += __shfl_xor_sync(0xffffffffu, p0, 1);
            p0 += __shfl_xor_sync(0xffffffffu, p0, 2);
            p1 += __shfl_xor_sync(0xffffffffu, p1, 1);
            p1 += __shfl_xor_sync(0xffffffffu, p1, 2);
            if (t == 0) {
                int row = m0 + wm*32 + mt*16 + g;
                atomicAdd(&C[row], p0);
                atomicAdd(&C[row + 8], p1);
            }
        }
        return;
    }

    #pragma unroll
    for (int mt = 0; mt < 2; mt++) {
        int row0 = m0 + wm*32 + mt*16 + g;
        #pragma unroll
        for (int nt = 0; nt < 8; nt++) {
            int col = n0 + wn*64 + nt*8 + t*2;
            float b0 = bias[col], b1 = bias[col+1];
            float v0 = acc[mt][nt][0] + b0;
            float v1 = acc[mt][nt][1] + b1;
            float v2 = acc[mt][nt][2] + b0;
            float v3 = acc[mt][nt][3] + b1;
            if (act == 1) {
                v0 = 1.f/(1.f+__expf(-v0)); v1 = 1.f/(1.f+__expf(-v1));
                v2 = 1.f/(1.f+__expf(-v2)); v3 = 1.f/(1.f+__expf(-v3));
            }
            *(float2*)&C[(size_t)row0*ldc + col]     = make_float2(v0, v1);
            *(float2*)&C[(size_t)(row0+8)*ldc + col] = make_float2(v2, v3);
        }
    }
}

// ---------------- flash attention (bf16x3, K/V from fused [row][512]) ----
#define QSP 36
#define KSS 72
#define VSS 68
#define SSS 68
#define SPP 36
#define ATT_WORDS (2*64*QSP + 64*KSS + 64*VSS + 64*SSS + 2*64*SPP + 3*64)
#define ATT_SMEM (ATT_WORDS*4)

__global__ __launch_bounds__(256, 2)
void attn_kernel(const float* __restrict__ Q, const float* __restrict__ KV,
                 float* __restrict__ O)
{
    extern __shared__ float sm[];
    unsigned* Qph = (unsigned*)sm;
    unsigned* Qpl = Qph + 64*QSP;
    float* KV0 = (float*)(Qpl + 64*QSP);
    float* KV1 = KV0 + 64*KSS;
    float* Sh  = KV1 + 64*VSS;
    unsigned* Sph = (unsigned*)(Sh + 64*SSS);
    unsigned* Spl = Sph + 64*SPP;
    float* mrow = (float*)(Spl + 64*SPP);
    float* lrow = mrow + 64;
    float* crow = lrow + 64;

    unsigned kv0s = (unsigned)__cvta_generic_to_shared(KV0);
    unsigned kv1s = (unsigned)__cvta_generic_to_shared(KV1);

    int qb = blockIdx.x, h = blockIdx.y, b = blockIdx.z;
    int tid = threadIdx.x;
    int q0 = qb * 64;

    int w = tid >> 5, lane = tid & 31;
    int g = lane >> 2, t = lane & 3;
    int wq = w >> 1, wk = w & 1;
    int q0r = wq*16, kc0 = wk*32;

    const float* Kbase = KV + ((size_t)(b*NSEQ))*KVLD + h*64;
    const float* Vbase = KV + ((size_t)(b*NSEQ))*KVLD + 256 + h*64;

    for (int i = tid; i < 64*16; i += 256) {
        int q = i >> 4, d4 = (i & 15) * 4;
        float4 v = *(const float4*)&Q[((size_t)(b*NSEQ + q0 + q))*DM + h*64 + d4];
        unsigned h0, l0, h1, l1;
        split2(v.x*0.125f, v.y*0.125f, h0, l0);
        split2(v.z*0.125f, v.w*0.125f, h1, l1);
        int pi = q*QSP + (d4 >> 1);
        Qph[pi] = h0; Qph[pi+1] = h1;
        Qpl[pi] = l0; Qpl[pi+1] = l1;
    }
    if (tid < 64) { mrow[tid] = -1e30f; lrow[tid] = 0.f; }

    #pragma unroll
    for (int i = 0; i < 4; i++) {
        int idx = tid + i*256;
        int row = idx >> 4, d4 = (idx & 15) * 4;
        cpa16(kv0s + (row*KSS + d4)*4, Kbase + (size_t)row*KVLD + d4);
    }
    CP_COMMIT();

    float oacc[4][4] = {};

    #pragma unroll 1
    for (int kt = 0; kt < 16; kt++) {
        #pragma unroll
        for (int i = 0; i < 4; i++) {
            int idx = tid + i*256;
            int row = idx >> 4, d4 = (idx & 15) * 4;
            cpa16(kv1s + (row*VSS + d4)*4, Vbase + (size_t)(kt*64 + row)*KVLD + d4);
        }
        CP_COMMIT();
        CP_WAIT1();
        __syncthreads();

        {
            float sacc[4][4] = {};
            #pragma unroll
            for (int dk = 0; dk < 64; dk += 16) {
                int kp = dk >> 1;
                unsigned qa[4], ql[4];
                {
                    const unsigned* ph = &Qph[(q0r + g)*QSP + kp + t];
                    const unsigned* pl = &Qpl[(q0r + g)*QSP + kp + t];
                    qa[0] = ph[0]; qa[1] = ph[8*QSP]; qa[2] = ph[4]; qa[3] = ph[8*QSP + 4];
                    ql[0] = pl[0]; ql[1] = pl[8*QSP]; ql[2] = pl[4]; ql[3] = pl[8*QSP + 4];
                }
                #pragma unroll
                for (int nt = 0; nt < 4; nt++) {
                    const float* p = &KV0[(kc0 + nt*8 + g)*KSS + dk + 2*t];
                    float2 y0 = *(const float2*)p;
                    float2 y1 = *(const float2*)(p + 8);
                    unsigned bh[2], bl[2];
                    split2(y0.x, y0.y, bh[0], bl[0]);
                    split2(y1.x, y1.y, bh[1], bl[1]);
                    mma16(sacc[nt], qa, bh);
                    mma16(sacc[nt], qa, bl);
                    mma16(sacc[nt], ql, bh);
                }
            }
            #pragma unroll
            for (int nt = 0; nt < 4; nt++) {
                int col = kc0 + nt*8 + t*2;
                *(float2*)&Sh[(q0r + g)*SSS + col]     = make_float2(sacc[nt][0], sacc[nt][1]);
                *(float2*)&Sh[(q0r + g + 8)*SSS + col] = make_float2(sacc[nt][2], sacc[nt][3]);
            }
        }
        __syncthreads();

        {
            int q = tid >> 2, part = tid & 3;
            int j0 = part * 16;
            float mold = mrow[q];
            float mx = mold;
            const float* row = Sh + q*SSS + j0;
            float pv[16];
            #pragma unroll
            for (int j = 0; j < 16; j++) { pv[j] = row[j]; mx = fmaxf(mx, pv[j]); }
            mx = fmaxf(mx, __shfl_xor_sync(0xffffffffu, mx, 1));
            mx = fmaxf(mx, __shfl_xor_sync(0xffffffffu, mx, 2));
            float ssum = 0.f;
            #pragma unroll
            for (int j = 0; j < 16; j++) { pv[j] = __expf(pv[j] - mx); ssum += pv[j]; }
            unsigned* oh = Sph + q*SPP + part*8;
            unsigned* ol = Spl + q*SPP + part*8;
            #pragma unroll
            for (int jj = 0; jj < 8; jj++) {
                unsigned hp, lp;
                split2(pv[2*jj], pv[2*jj+1], hp, lp);
                oh[jj] = hp; ol[jj] = lp;
            }
            ssum += __shfl_xor_sync(0xffffffffu, ssum, 1);
            ssum += __shfl_xor_sync(0xffffffffu, ssum, 2);
            if (part == 0) {
                float corr = __expf(mold - mx);
                lrow[q] = lrow[q]*corr + ssum;
                mrow[q] = mx;
                crow[q] = corr;
            }
        }
        __syncthreads();
        CP_WAIT0();
        __syncthreads();

        if (kt < 15) {
            #pragma unroll
            for (int i = 0; i < 4; i++) {
                int idx = tid + i*256;
                int row = idx >> 4, d4 = (idx & 15) * 4;
                cpa16(kv0s + (row*KSS + d4)*4, Kbase + (size_t)((kt+1)*64 + row)*KVLD + d4);
            }
            CP_COMMIT();
        }

        {
            float c0 = crow[q0r + g];
            float c1 = crow[q0r + g + 8];
            #pragma unroll
            for (int nt = 0; nt < 4; nt++) {
                oacc[nt][0] *= c0; oacc[nt][1] *= c0;
                oacc[nt][2] *= c1; oacc[nt][3] *= c1;
            }
            #pragma unroll
            for (int kk = 0; kk < 64; kk += 16) {
                int kp = kk >> 1;
                unsigned pa[4], pl[4];
                {
                    const unsigned* ph = &Sph[(q0r + g)*SPP + kp + t];
                    const unsigned* pq = &Spl[(q0r + g)*SPP + kp + t];
                    pa[0] = ph[0]; pa[1] = ph[8*SPP]; pa[2] = ph[4]; pa[3] = ph[8*SPP + 4];
                    pl[0] = pq[0]; pl[1] = pq[8*SPP]; pl[2] = pq[4]; pl[3] = pq[8*SPP + 4];
                }
                #pragma unroll
                for (int nt = 0; nt < 4; nt++) {
                    int dcol = kc0 + nt*8 + g;
                    float v0 = KV1[(kk + 2*t)*VSS + dcol];
                    float v1 = KV1[(kk + 2*t + 1)*VSS + dcol];
                    float v2 = KV1[(kk + 2*t + 8)*VSS + dcol];
                    float v3 = KV1[(kk + 2*t + 9)*VSS + dcol];
                    unsigned vh[2], vl[2];
                    split2(v0, v1, vh[0], vl[0]);
                    split2(v2, v3, vh[1], vl[1]);
                    mma16(oacc[nt], pa, vh);
                    mma16(oacc[nt], pa, vl);
                    mma16(oacc[nt], pl, vh);
                }
            }
        }
        __syncthreads();
    }

    float inv0 = 1.f / lrow[q0r + g];
    float inv1 = 1.f / lrow[q0r + g + 8];
    #pragma unroll
    for (int nt = 0; nt < 4; nt++) {
        int col = kc0 + nt*8 + t*2;
        *(float2*)&O[((size_t)(b*NSEQ + q0 + q0r + g))*DM + h*64 + col] =
            make_float2(oacc[nt][0]*inv0, oacc[nt][1]*inv0);
        *(float2*)&O[((size_t)(b*NSEQ + q0 + q0r + g + 8))*DM + h*64 + col] =
            make_float2(oacc[nt][2]*inv1, oacc[nt][3]*inv1);
    }
}

// ---------------- out init ----------------
__global__ void init_out_kernel(float* __restrict__ out, const float* __restrict__ b2)
{
    int i = blockIdx.x*256 + threadIdx.x;
    out[i] = b2[0];
}

// ---------------- host launch ----------------
extern "C" void kernel_launch(void* const* d_in, const int* in_sizes, int n_in,
                              void* d_out, int out_size)
{
    const float* sparse_coords = (const float*)d_in[0];
    const float* sparse_values = (const float*)d_in[1];
    const float* query_coords  = (const float*)d_in[2];
    const float* t_in          = (const float*)d_in[3];
    const float* noise         = (const float*)d_in[4];
    const float* B_f           = (const float*)d_in[5];
    const float* Wq_in         = (const float*)d_in[6];
    const float* bq_in         = (const float*)d_in[7];
    const float* Wi_in         = (const float*)d_in[8];
    const float* bi_in         = (const float*)d_in[9];
    const float* A_log         = (const float*)d_in[10];
    const float* Bw            = (const float*)d_in[11];
    const float* Cw            = (const float*)d_in[12];
    const float* Dp            = (const float*)d_in[13];
    const float* ln_g          = (const float*)d_in[14];
    const float* ln_b          = (const float*)d_in[15];
    const float* gate_w        = (const float*)d_in[16];
    const float* gate_b        = (const float*)d_in[17];
    const float* in_proj_w     = (const float*)d_in[18];
    const float* in_proj_b     = (const float*)d_in[19];
    const float* out_w         = (const float*)d_in[20];
    const float* out_b         = (const float*)d_in[21];
    const float* dec_w1        = (const float*)d_in[22];
    const float* dec_b1        = (const float*)d_in[23];
    const float* dec_w2        = (const float*)d_in[24];
    const float* dec_b2        = (const float*)d_in[25];
    float* out = (float*)d_out;

    float *p_seq, *p_xn, *p_gate, *p_bu, *p_hs, *p_q, *p_kv, *p_att, *p_wc, *p_bc;
    unsigned *p_wh, *p_wl;
    cudaGetSymbolAddress((void**)&p_seq, g_seq);
    cudaGetSymbolAddress((void**)&p_xn,  g_xn);
    cudaGetSymbolAddress((void**)&p_gate,g_gate);
    cudaGetSymbolAddress((void**)&p_bu,  g_bu);
    cudaGetSymbolAddress((void**)&p_hs,  g_hs);
    cudaGetSymbolAddress((void**)&p_q,   g_q);
    cudaGetSymbolAddress((void**)&p_kv,  g_kv);
    cudaGetSymbolAddress((void**)&p_att, g_att);
    cudaGetSymbolAddress((void**)&p_wc,  g_wc);
    cudaGetSymbolAddress((void**)&p_bc,  g_bc);
    cudaGetSymbolAddress((void**)&p_wh,  g_wh);
    cudaGetSymbolAddress((void**)&p_wl,  g_wl);

    cudaFuncSetAttribute(attn_kernel, cudaFuncAttributeMaxDynamicSharedMemorySize, ATT_SMEM);

    int ntok_all = BATCH*NTOK;          // 32768
    int nq_all   = BATCH*NSEQ;          // 16384
    const int BIGR = 1 << 30;

    // prep: out init + weight pack + fold (out untouched until dec gemm)
    init_out_kernel<<<nq_all/256, 256>>>(out, dec_b2);
    pack_kernel<<<(131072+255)/256, 256>>>(gate_w,    p_wh + OFF_GATE,   p_wl + OFF_GATE,   131072);
    pack_kernel<<<( 98304+255)/256, 256>>>(in_proj_w, p_wh + OFF_INPROJ, p_wl + OFF_INPROJ,  98304);
    comb_wb_kernel<<<DM, DM>>>(dec_w1, out_w, out_b, dec_b1, p_wc, p_bc);
    pack_kernel<<<(32768+255)/256, 256>>>(p_wc, p_wh + OFF_DEC, p_wl + OFF_DEC, 32768);

    embed_ln_bu_kernel<<<ntok_all, 256>>>(sparse_coords, sparse_values, query_coords, t_in,
                                          noise, B_f, Wq_in, bq_in, Wi_in, bi_in,
                                          ln_g, ln_b, Bw, p_seq, p_xn, p_bu);

    for (int l = 0; l < NLAYER; l++) {
        gemm_tc<<<dim3(2, ntok_all/128 + 64), 256>>>(p_xn,
                                                p_wh + OFF_GATE + l*32768, p_wl + OFF_GATE + l*32768,
                                                gate_b + l*DM, p_gate, nullptr,
                                                A_log + l*NSTATE, p_bu, p_hs,
                                                BIGR, 0, 0, DM, 1);
        if (l < NLAYER-1) {
            ssm_ln_bu_kernel<<<ntok_all, 256>>>(Cw + l*DM*NSTATE, Dp + l*DM,
                                                p_xn, p_hs, p_gate, p_seq,
                                                ln_g + (l+1)*DM, ln_b + (l+1)*DM,
                                                Bw + (l+1)*NSTATE*DM,
                                                p_xn, p_bu);
        } else {
            ssm_out_kernel<<<ntok_all, 256>>>(Cw + l*DM*NSTATE, Dp + l*DM,
                                              p_xn, p_hs, p_gate, p_seq);
        }
    }

    // q projection (query-half rows)
    gemm_tc<<<dim3(2, nq_all/128), 256>>>(p_seq, p_wh + OFF_INPROJ, p_wl + OFF_INPROJ,
                                          in_proj_b, p_q, nullptr, nullptr, nullptr, nullptr,
                                          NSEQ, NTOK, NSEQ, DM, 0);
    // fused k|v projection: N=512, input-half rows, C=[row][512]
    gemm_tc<<<dim3(4, nq_all/128), 256>>>(p_seq, p_wh + OFF_INPROJ + 32768, p_wl + OFF_INPROJ + 32768,
                                          in_proj_b + DM, p_kv, nullptr, nullptr, nullptr, nullptr,
                                          NSEQ, NTOK, 0, KVLD, 0);

    attn_kernel<<<dim3(16, 4, BATCH), 256, ATT_SMEM>>>(p_q, p_kv, p_att);

    gemm_tc<<<dim3(2, nq_all/128), 256>>>(p_att, p_wh + OFF_DEC, p_wl + OFF_DEC,
                                          p_bc, out, dec_w2, nullptr, nullptr, nullptr,
                                          BIGR, 0, 0, DM, 3);
}

// round 16
// speedup vs baseline: 1.0283x; 1.0011x over previous
#include <cuda_runtime.h>
#include <cstdint>

#define BATCH 16
#define NSEQ  1024
#define NTOK  2048
#define DM    256
#define NLAYER 4
#define NSTATE 8
#define NF    16
#define CIN   33
#define LN_EPS 1e-5f
#define KVLD  512

// ---------------- scratch ----------------
__device__ float g_seq [BATCH*NTOK*DM];
__device__ float g_xn  [BATCH*NTOK*DM];
__device__ float g_gate[BATCH*NTOK*DM];
__device__ float g_bu  [BATCH*NSTATE*NTOK];
__device__ float g_hs  [BATCH*NSTATE*NTOK];
__device__ float g_q   [BATCH*NSEQ*DM];
__device__ float g_kv  [BATCH*NSEQ*KVLD];
__device__ float g_att [BATCH*NSEQ*DM];
__device__ float g_wc  [DM*DM];
__device__ float g_bc  [DM];
__device__ unsigned g_wh[294912];
__device__ unsigned g_wl[294912];

#define OFF_GATE   0
#define OFF_INPROJ 131072
#define OFF_DEC    262144

// ---------------- bf16 split helpers ----------------
__device__ __forceinline__ unsigned packbf(float x0, float x1) {
    unsigned r;
    asm("cvt.rn.bf16x2.f32 %0, %1, %2;" : "=r"(r) : "f"(x1), "f"(x0));
    return r;
}
__device__ __forceinline__ void split2(float x0, float x1, unsigned& h, unsigned& l) {
    h = packbf(x0, x1);
    float h0 = __uint_as_float(h << 16);
    float h1 = __uint_as_float(h & 0xFFFF0000u);
    l = packbf(x0 - h0, x1 - h1);
}
__device__ __forceinline__ void mma16(float (&d)[4], const unsigned* a, const unsigned* b) {
    asm volatile("mma.sync.aligned.m16n8k16.row.col.f32.bf16.bf16.f32 "
        "{%0,%1,%2,%3}, {%4,%5,%6,%7}, {%8,%9}, {%0,%1,%2,%3};"
        : "+f"(d[0]), "+f"(d[1]), "+f"(d[2]), "+f"(d[3])
        : "r"(a[0]), "r"(a[1]), "r"(a[2]), "r"(a[3]), "r"(b[0]), "r"(b[1]));
}
__device__ __forceinline__ void cpa16(unsigned s, const void* g) {
    asm volatile("cp.async.cg.shared.global [%0], [%1], 16;" :: "r"(s), "l"(g));
}
#define CP_COMMIT() asm volatile("cp.async.commit_group;")
#define CP_WAIT0()  asm volatile("cp.async.wait_group 0;")
#define CP_WAIT1()  asm volatile("cp.async.wait_group 1;")

// ---------------- weight pack ----------------
__global__ void pack_kernel(const float* __restrict__ src,
                            unsigned* __restrict__ dh, unsigned* __restrict__ dl,
                            int npairs)
{
    int i = blockIdx.x*256 + threadIdx.x;
    if (i < npairs) {
        float2 v = ((const float2*)src)[i];
        unsigned h, l; split2(v.x, v.y, h, l);
        dh[i] = h; dl[i] = l;
    }
}

// ---------------- combine out_w into dec_w1 (+ bias fold) ----------------
__global__ void comb_wb_kernel(const float* __restrict__ w1,
                               const float* __restrict__ ow,
                               const float* __restrict__ ob,
                               const float* __restrict__ b1,
                               float* __restrict__ wc,
                               float* __restrict__ bc)
{
    __shared__ float row[DM];
    __shared__ float red[8];
    int i = blockIdx.x, j = threadIdx.x;
    row[j] = w1[i*DM + j];
    __syncthreads();
    float s = 0.f;
    #pragma unroll 8
    for (int k = 0; k < DM; k++) s += row[k] * ow[k*DM + j];
    wc[i*DM + j] = s;

    float p = row[j] * ob[j];
    #pragma unroll
    for (int o = 16; o; o >>= 1) p += __shfl_xor_sync(0xffffffffu, p, o);
    if ((j & 31) == 0) red[j >> 5] = p;
    __syncthreads();
    if (j == 0) {
        float t = b1[i];
        #pragma unroll
        for (int k = 0; k < 8; k++) t += red[k];
        bc[i] = t;
    }
}

// ---------------- LN + Bu core ----------------
__device__ __forceinline__ void ln_bu_body(float x, int token, int tid,
                                           const float* __restrict__ lng,
                                           const float* __restrict__ lnb,
                                           const float* __restrict__ Bw,
                                           float* __restrict__ xn_out,
                                           float* __restrict__ bu_out,
                                           float* xs, float* part)
{
    int w = tid >> 5, lane = tid & 31;
    float s = x;
    #pragma unroll
    for (int o = 16; o; o >>= 1) s += __shfl_xor_sync(0xffffffffu, s, o);
    if (lane == 0) part[w] = s;
    __syncthreads();
    float mu = 0.f;
    #pragma unroll
    for (int i = 0; i < 8; i++) mu += part[i];
    mu *= (1.f/256.f);
    float dx = x - mu;
    float s2 = dx*dx;
    #pragma unroll
    for (int o = 16; o; o >>= 1) s2 += __shfl_xor_sync(0xffffffffu, s2, o);
    __syncthreads();
    if (lane == 0) part[8 + w] = s2;
    __syncthreads();
    float var = 0.f;
    #pragma unroll
    for (int i = 0; i < 8; i++) var += part[8 + i];
    var *= (1.f/256.f);

    float xn = dx * rsqrtf(var + LN_EPS) * lng[tid] + lnb[tid];
    xn_out[(size_t)token*DM + tid] = xn;
    xs[tid] = xn;
    __syncthreads();

    float bs = 0.f;
    #pragma unroll
    for (int i = 0; i < 8; i++) {
        int d = lane + i*32;
        bs += xs[d] * Bw[w*DM + d];
    }
    #pragma unroll
    for (int o = 16; o; o >>= 1) bs += __shfl_xor_sync(0xffffffffu, bs, o);
    if (lane == 0) {
        int b = token >> 11, n = token & 2047;
        bu_out[((size_t)(b*NSTATE + w))*NTOK + n] = bs;
    }
}

// ---------------- fused embed + LN + Bu ----------------
__global__ void embed_ln_bu_kernel(const float* __restrict__ sparse_coords,
                                   const float* __restrict__ sparse_values,
                                   const float* __restrict__ query_coords,
                                   const float* __restrict__ t_in,
                                   const float* __restrict__ noise,
                                   const float* __restrict__ B_f,
                                   const float* __restrict__ Wq, const float* __restrict__ bq,
                                   const float* __restrict__ Wi, const float* __restrict__ bi,
                                   const float* __restrict__ lng, const float* __restrict__ lnb,
                                   const float* __restrict__ Bw,
                                   float* __restrict__ seq,
                                   float* __restrict__ xn_out, float* __restrict__ bu_out)
{
    __shared__ float feat[CIN];
    __shared__ float xs[DM];
    __shared__ float part[16];
    int token = blockIdx.x;
    int b = token / NTOK;
    int n = token % NTOK;
    int tid = threadIdx.x;

    const float* W; const float* bias;
    float cx, cy, val;
    if (n < NSEQ) {
        cx = sparse_coords[(b*NSEQ + n)*2 + 0];
        cy = sparse_coords[(b*NSEQ + n)*2 + 1];
        val = sparse_values[b*NSEQ + n];
        W = Wi; bias = bi;
    } else {
        int m = n - NSEQ;
        cx = query_coords[(b*NSEQ + m)*2 + 0];
        cy = query_coords[(b*NSEQ + m)*2 + 1];
        val = noise[b*NSEQ + m];
        W = Wq; bias = bq;
    }
    if (tid < NF) {
        float proj = cx * B_f[tid] + cy * B_f[NF + tid];
        feat[tid]      = sinf(proj);
        feat[NF + tid] = cosf(proj);
    }
    if (tid == 0) feat[2*NF] = val;
    __syncthreads();

    int d = tid;
    float acc = bias[d];
    const float* wrow = W + d*CIN;
    #pragma unroll
    for (int k = 0; k < CIN; k++) acc += feat[k] * wrow[k];

    float tv = t_in[b];
    float e;
    if (d < 128) e = sinf(tv * expf((float)d * (-9.210340371976184f / 127.f)));
    else         e = cosf(tv * expf((float)(d-128) * (-9.210340371976184f / 127.f)));

    float x = acc + e;
    seq[(size_t)token*DM + d] = x;
    __syncthreads();
    ln_bu_body(x, token, tid, lng, lnb, Bw, xn_out, bu_out, xs, part);
}

// ---------------- fused: ssm_out(l) + ln_bu(l+1) ----------------
__global__ void ssm_ln_bu_kernel(const float* __restrict__ Cw, const float* __restrict__ Dp,
                                 const float* __restrict__ xn, const float* __restrict__ hs,
                                 const float* __restrict__ gate, float* __restrict__ seq,
                                 const float* __restrict__ lng2, const float* __restrict__ lnb2,
                                 const float* __restrict__ Bw2,
                                 float* __restrict__ xn_out, float* __restrict__ bu_out)
{
    __shared__ float xs[DM];
    __shared__ float part[16];
    __shared__ float hsl[NSTATE];
    int token = blockIdx.x;
    int tid = threadIdx.x;
    if (tid < NSTATE) {
        int b = token >> 11, n = token & 2047;
        hsl[tid] = hs[((size_t)(b*NSTATE + tid))*NTOK + n];
    }
    __syncthreads();
    size_t idx = (size_t)token*DM + tid;
    float xv = xn[idx];
    float o = Dp[tid] * xv;
    #pragma unroll
    for (int s = 0; s < NSTATE; s++) o += hsl[s] * Cw[tid*NSTATE + s];
    float x = seq[idx] + gate[idx] * o;
    seq[idx] = x;
    __syncthreads();
    ln_bu_body(x, token, tid, lng2, lnb2, Bw2, xn_out, bu_out, xs, part);
}

// ---------------- last-layer ssm_out ----------------
__global__ void ssm_out_kernel(const float* __restrict__ Cw, const float* __restrict__ Dp,
                               const float* __restrict__ xn, const float* __restrict__ hs,
                               const float* __restrict__ gate, float* __restrict__ seq)
{
    int token = blockIdx.x;
    int tid = threadIdx.x;
    __shared__ float hsl[NSTATE];
    if (tid < NSTATE) {
        int b = token >> 11, n = token & 2047;
        hsl[tid] = hs[((size_t)(b*NSTATE + tid))*NTOK + n];
    }
    __syncthreads();
    size_t idx = (size_t)token*DM + tid;
    float xv = xn[idx];
    float o = Dp[tid] * xv;
    #pragma unroll
    for (int s = 0; s < NSTATE; s++) o += hsl[s] * Cw[tid*NSTATE + s];
    seq[idx] += gate[idx] * o;
}

// ---------------- tensor-core GEMM (bf16x3, pre-packed B) ----------------
// act: 0=none 1=sigmoid(+fused scan in extra y-blocks) 3=relu+dot(w2)->atomicAdd
#define GSK 24
#define BSP 12
__global__ __launch_bounds__(256, 2)
void gemm_tc(const float* __restrict__ A,
             const unsigned* __restrict__ Wh, const unsigned* __restrict__ Wl,
             const float* __restrict__ bias, float* __restrict__ C,
             const float* __restrict__ w2,
             const float* __restrict__ A_log,
             const float* __restrict__ bu, float* __restrict__ hs,
             int rpb, int tstride, int rowoff, int ldc, int act)
{
    __shared__ float As[2][128*GSK];
    __shared__ unsigned sBh[2][128*BSP];
    __shared__ unsigned sBl[2][128*BSP];
    __shared__ float sb[NTOK];

    int tid = threadIdx.x;

    // ---- fused scan blocks (gate launch only: blockIdx.y >= 256) ----
    if (blockIdx.y >= 256) {
        if (tid < 32) {
            int wi = (blockIdx.y - 256) * 2 + blockIdx.x;   // 0..127
            int lane = tid;
            int s = wi & 7;
            float Av = -fminf(fmaxf(expf(A_log[s]), 1e-8f), 10.f);
            float Abar = expf(Av * (1.f/2048.f));
            float p64  = expf(Av * (1.f/32.f));
            const float* bup = bu + (size_t)wi*NTOK;
            float* hsp = hs + (size_t)wi*NTOK;
            #pragma unroll
            for (int i = 0; i < 64; i++) sb[lane + i*32] = bup[lane + i*32];
            __syncwarp();
            int base = lane * 64;
            float loc = 0.f;
            #pragma unroll 8
            for (int i = 0; i < 64; i++) loc = Abar*loc + sb[base + i];
            float aa = p64, bb = loc;
            #pragma unroll
            for (int off = 1; off < 32; off <<= 1) {
                float pa = __shfl_up_sync(0xffffffffu, aa, off);
                float pb = __shfl_up_sync(0xffffffffu, bb, off);
                if (lane >= off) { bb = aa*pb + bb; aa = aa*pa; }
            }
            float hin = __shfl_up_sync(0xffffffffu, bb, 1);
            if (lane == 0) hin = 0.f;
            float h = hin;
            #pragma unroll 8
            for (int i = 0; i < 64; i++) {
                h = Abar*h + sb[base + i];
                sb[base + i] = h;
            }
            __syncwarp();
            #pragma unroll
            for (int i = 0; i < 64; i++) hsp[lane + i*32] = sb[lane + i*32];
        }
        return;
    }

    int m0 = blockIdx.y * 128, n0 = blockIdx.x * 128;

    int r  = tid >> 1;
    int cb = (tid & 1) * 8;
    int h4 = (tid & 1) * 4;
    int m = m0 + r;
    int tok = (m / rpb) * tstride + rowoff + (m % rpb);
    const float*    Aptr  = A  + (size_t)tok*DM + cb;
    const unsigned* Bptrh = Wh + (size_t)(n0 + r)*128 + h4;
    const unsigned* Bptrl = Wl + (size_t)(n0 + r)*128 + h4;

    int w = tid >> 5, lane = tid & 31;
    int g = lane >> 2, t = lane & 3;
    int wm = w >> 1, wn = w & 1;

    float acc[2][8][4] = {};

    {
        float4 a0 = *(const float4*)Aptr;
        float4 a1 = *(const float4*)(Aptr + 4);
        uint4  b0 = *(const uint4*)Bptrh;
        uint4  b1 = *(const uint4*)Bptrl;
        *(float4*)&As[0][r*GSK + cb]     = a0;
        *(float4*)&As[0][r*GSK + cb + 4] = a1;
        *(uint4*)&sBh[0][r*BSP + h4] = b0;
        *(uint4*)&sBl[0][r*BSP + h4] = b1;
    }
    __syncthreads();

    #pragma unroll 1
    for (int ck = 0; ck < 16; ck++) {
        int buf = ck & 1;
        float4 a0, a1; uint4 nb0, nb1;
        if (ck < 15) {
            a0  = *(const float4*)(Aptr + (ck+1)*16);
            a1  = *(const float4*)(Aptr + (ck+1)*16 + 4);
            nb0 = *(const uint4*)(Bptrh + (ck+1)*8);
            nb1 = *(const uint4*)(Bptrl + (ck+1)*8);
        }

        unsigned ah[2][4], al[2][4];
        #pragma unroll
        for (int mt = 0; mt < 2; mt++) {
            const float* p = &As[buf][(wm*32 + mt*16 + g)*GSK + 2*t];
            float2 x0 = *(const float2*)p;
            float2 x1 = *(const float2*)(p + 8*GSK);
            float2 x2 = *(const float2*)(p + 8);
            float2 x3 = *(const float2*)(p + 8*GSK + 8);
            split2(x0.x, x0.y, ah[mt][0], al[mt][0]);
            split2(x1.x, x1.y, ah[mt][1], al[mt][1]);
            split2(x2.x, x2.y, ah[mt][2], al[mt][2]);
            split2(x3.x, x3.y, ah[mt][3], al[mt][3]);
        }
        #pragma unroll
        for (int nt = 0; nt < 8; nt++) {
            int bi = (wn*64 + nt*8 + g)*BSP + t;
            unsigned bh[2], bl[2];
            bh[0] = sBh[buf][bi]; bh[1] = sBh[buf][bi + 4];
            bl[0] = sBl[buf][bi]; bl[1] = sBl[buf][bi + 4];
            #pragma unroll
            for (int mt = 0; mt < 2; mt++) {
                mma16(acc[mt][nt], ah[mt], bh);
                mma16(acc[mt][nt], ah[mt], bl);
                mma16(acc[mt][nt], al[mt], bh);
            }
        }

        if (ck < 15) {
            int nb = buf ^ 1;
            *(float4*)&As[nb][r*GSK + cb]     = a0;
            *(float4*)&As[nb][r*GSK + cb + 4] = a1;
            *(uint4*)&sBh[nb][r*BSP + h4] = nb0;
            *(uint4*)&sBl[nb][r*BSP + h4] = nb1;
            __syncthreads();
        }
    }

    if (act == 3) {
        #pragma unroll
        for (int mt = 0; mt < 2; mt++) {
            float p0 = 0.f, p1 = 0.f;
            #pragma unroll
            for (int nt = 0; nt < 8; nt++) {
                int col = n0 + wn*64 + nt*8 + t*2;
                float b0 = bias[col], b1 = bias[col+1];
                float w0 = w2[col],  w1 = w2[col+1];
                p0 += fmaxf(acc[mt][nt][0] + b0, 0.f)*w0 + fmaxf(acc[mt][nt][1] + b1, 0.f)*w1;
                p1 += fmaxf(acc[mt][nt][2] + b0, 0.f)*w0 + fmaxf(acc[mt][nt][3] + b1, 0.f)*w1;
            }
            p0 += __shfl_xor_sync(0xffffffffu, p0, 1);
            p0 += __shfl_xor_sync(0xffffffffu, p0, 2);
            p1 += __shfl_xor_sync(0xffffffffu, p1, 1);
            p1 += __shfl_xor_sync(0xffffffffu, p1, 2);
            if (t == 0) {
                int row = m0 + wm*32 + mt*16 + g;
                atomicAdd(&C[row], p0);
                atomicAdd(&C[row + 8], p1);
            }
        }
        return;
    }

    #pragma unroll
    for (int mt = 0; mt < 2; mt++) {
        int row0 = m0 + wm*32 + mt*16 + g;
        #pragma unroll
        for (int nt = 0; nt < 8; nt++) {
            int col = n0 + wn*64 + nt*8 + t*2;
            float b0 = bias[col], b1 = bias[col+1];
            float v0 = acc[mt][nt][0] + b0;
            float v1 = acc[mt][nt][1] + b1;
            float v2 = acc[mt][nt][2] + b0;
            float v3 = acc[mt][nt][3] + b1;
            if (act == 1) {
                v0 = 1.f/(1.f+__expf(-v0)); v1 = 1.f/(1.f+__expf(-v1));
                v2 = 1.f/(1.f+__expf(-v2)); v3 = 1.f/(1.f+__expf(-v3));
            }
            *(float2*)&C[(size_t)row0*ldc + col]     = make_float2(v0, v1);
            *(float2*)&C[(size_t)(row0+8)*ldc + col] = make_float2(v2, v3);
        }
    }
}

// ---------------- flash attention (bf16x3, K/V from fused [row][512]) ----
#define QSP 36
#define KSS 72
#define VSS 68
#define SSS 68
#define SPP 36
#define ATT_WORDS (2*64*QSP + 64*KSS + 64*VSS + 64*SSS + 2*64*SPP + 3*64)
#define ATT_SMEM (ATT_WORDS*4)

__global__ __launch_bounds__(256, 2)
void attn_kernel(const float* __restrict__ Q, const float* __restrict__ KV,
                 float* __restrict__ O)
{
    extern __shared__ float sm[];
    unsigned* Qph = (unsigned*)sm;
    unsigned* Qpl = Qph + 64*QSP;
    float* KV0 = (float*)(Qpl + 64*QSP);
    float* KV1 = KV0 + 64*KSS;
    float* Sh  = KV1 + 64*VSS;
    unsigned* Sph = (unsigned*)(Sh + 64*SSS);
    unsigned* Spl = Sph + 64*SPP;
    float* mrow = (float*)(Spl + 64*SPP);
    float* lrow = mrow + 64;
    float* crow = lrow + 64;

    unsigned kv0s = (unsigned)__cvta_generic_to_shared(KV0);
    unsigned kv1s = (unsigned)__cvta_generic_to_shared(KV1);

    int qb = blockIdx.x, h = blockIdx.y, b = blockIdx.z;
    int tid = threadIdx.x;
    int q0 = qb * 64;

    int w = tid >> 5, lane = tid & 31;
    int g = lane >> 2, t = lane & 3;
    int wq = w >> 1, wk = w & 1;
    int q0r = wq*16, kc0 = wk*32;

    const float* Kbase = KV + ((size_t)(b*NSEQ))*KVLD + h*64;
    const float* Vbase = KV + ((size_t)(b*NSEQ))*KVLD + 256 + h*64;

    for (int i = tid; i < 64*16; i += 256) {
        int q = i >> 4, d4 = (i & 15) * 4;
        float4 v = *(const float4*)&Q[((size_t)(b*NSEQ + q0 + q))*DM + h*64 + d4];
        unsigned h0, l0, h1, l1;
        split2(v.x*0.125f, v.y*0.125f, h0, l0);
        split2(v.z*0.125f, v.w*0.125f, h1, l1);
        int pi = q*QSP + (d4 >> 1);
        Qph[pi] = h0; Qph[pi+1] = h1;
        Qpl[pi] = l0; Qpl[pi+1] = l1;
    }
    if (tid < 64) { mrow[tid] = -1e30f; lrow[tid] = 0.f; }

    #pragma unroll
    for (int i = 0; i < 4; i++) {
        int idx = tid + i*256;
        int row = idx >> 4, d4 = (idx & 15) * 4;
        cpa16(kv0s + (row*KSS + d4)*4, Kbase + (size_t)row*KVLD + d4);
    }
    CP_COMMIT();

    float oacc[4][4] = {};

    #pragma unroll 1
    for (int kt = 0; kt < 16; kt++) {
        #pragma unroll
        for (int i = 0; i < 4; i++) {
            int idx = tid + i*256;
            int row = idx >> 4, d4 = (idx & 15) * 4;
            cpa16(kv1s + (row*VSS + d4)*4, Vbase + (size_t)(kt*64 + row)*KVLD + d4);
        }
        CP_COMMIT();
        CP_WAIT1();
        __syncthreads();

        {
            float sacc[4][4] = {};
            #pragma unroll
            for (int dk = 0; dk < 64; dk += 16) {
                int kp = dk >> 1;
                unsigned qa[4], ql[4];
                {
                    const unsigned* ph = &Qph[(q0r + g)*QSP + kp + t];
                    const unsigned* pl = &Qpl[(q0r + g)*QSP + kp + t];
                    qa[0] = ph[0]; qa[1] = ph[8*QSP]; qa[2] = ph[4]; qa[3] = ph[8*QSP + 4];
                    ql[0] = pl[0]; ql[1] = pl[8*QSP]; ql[2] = pl[4]; ql[3] = pl[8*QSP + 4];
                }
                #pragma unroll
                for (int nt = 0; nt < 4; nt++) {
                    const float* p = &KV0[(kc0 + nt*8 + g)*KSS + dk + 2*t];
                    float2 y0 = *(const float2*)p;
                    float2 y1 = *(const float2*)(p + 8);
                    unsigned bh[2], bl[2];
                    split2(y0.x, y0.y, bh[0], bl[0]);
                    split2(y1.x, y1.y, bh[1], bl[1]);
                    mma16(sacc[nt], qa, bh);
                    mma16(sacc[nt], qa, bl);
                    mma16(sacc[nt], ql, bh);
                }
            }
            #pragma unroll
            for (int nt = 0; nt < 4; nt++) {
                int col = kc0 + nt*8 + t*2;
                *(float2*)&Sh[(q0r + g)*SSS + col]     = make_float2(sacc[nt][0], sacc[nt][1]);
                *(float2*)&Sh[(q0r + g + 8)*SSS + col] = make_float2(sacc[nt][2], sacc[nt][3]);
            }
        }
        __syncthreads();

        {
            int q = tid >> 2, part = tid & 3;
            int j0 = part * 16;
            float mold = mrow[q];
            float mx = mold;
            const float* row = Sh + q*SSS + j0;
            float pv[16];
            #pragma unroll
            for (int j = 0; j < 16; j++) { pv[j] = row[j]; mx = fmaxf(mx, pv[j]); }
            mx = fmaxf(mx, __shfl_xor_sync(0xffffffffu, mx, 1));
            mx = fmaxf(mx, __shfl_xor_sync(0xffffffffu, mx, 2));
            float ssum = 0.f;
            #pragma unroll
            for (int j = 0; j < 16; j++) { pv[j] = __expf(pv[j] - mx); ssum += pv[j]; }
            unsigned* oh = Sph + q*SPP + part*8;
            unsigned* ol = Spl + q*SPP + part*8;
            #pragma unroll
            for (int jj = 0; jj < 8; jj++) {
                unsigned hp, lp;
                split2(pv[2*jj], pv[2*jj+1], hp, lp);
                oh[jj] = hp; ol[jj] = lp;
            }
            ssum += __shfl_xor_sync(0xffffffffu, ssum, 1);
            ssum += __shfl_xor_sync(0xffffffffu, ssum, 2);
            if (part == 0) {
                float corr = __expf(mold - mx);
                lrow[q] = lrow[q]*corr + ssum;
                mrow[q] = mx;
                crow[q] = corr;
            }
        }
        __syncthreads();
        CP_WAIT0();
        __syncthreads();

        if (kt < 15) {
            #pragma unroll
            for (int i = 0; i < 4; i++) {
                int idx = tid + i*256;
                int row = idx >> 4, d4 = (idx & 15) * 4;
                cpa16(kv0s + (row*KSS + d4)*4, Kbase + (size_t)((kt+1)*64 + row)*KVLD + d4);
            }
            CP_COMMIT();
        }

        {
            float c0 = crow[q0r + g];
            float c1 = crow[q0r + g + 8];
            #pragma unroll
            for (int nt = 0; nt < 4; nt++) {
                oacc[nt][0] *= c0; oacc[nt][1] *= c0;
                oacc[nt][2] *= c1; oacc[nt][3] *= c1;
            }
            #pragma unroll
            for (int kk = 0; kk < 64; kk += 16) {
                int kp = kk >> 1;
                unsigned pa[4], pl[4];
                {
                    const unsigned* ph = &Sph[(q0r + g)*SPP + kp + t];
                    const unsigned* pq = &Spl[(q0r + g)*SPP + kp + t];
                    pa[0] = ph[0]; pa[1] = ph[8*SPP]; pa[2] = ph[4]; pa[3] = ph[8*SPP + 4];
                    pl[0] = pq[0]; pl[1] = pq[8*SPP]; pl[2] = pq[4]; pl[3] = pq[8*SPP + 4];
                }
                #pragma unroll
                for (int nt = 0; nt < 4; nt++) {
                    int dcol = kc0 + nt*8 + g;
                    float v0 = KV1[(kk + 2*t)*VSS + dcol];
                    float v1 = KV1[(kk + 2*t + 1)*VSS + dcol];
                    float v2 = KV1[(kk + 2*t + 8)*VSS + dcol];
                    float v3 = KV1[(kk + 2*t + 9)*VSS + dcol];
                    unsigned vh[2], vl[2];
                    split2(v0, v1, vh[0], vl[0]);
                    split2(v2, v3, vh[1], vl[1]);
                    mma16(oacc[nt], pa, vh);
                    mma16(oacc[nt], pa, vl);
                    mma16(oacc[nt], pl, vh);
                }
            }
        }
        __syncthreads();
    }

    float inv0 = 1.f / lrow[q0r + g];
    float inv1 = 1.f / lrow[q0r + g + 8];
    #pragma unroll
    for (int nt = 0; nt < 4; nt++) {
        int col = kc0 + nt*8 + t*2;
        *(float2*)&O[((size_t)(b*NSEQ + q0 + q0r + g))*DM + h*64 + col] =
            make_float2(oacc[nt][0]*inv0, oacc[nt][1]*inv0);
        *(float2*)&O[((size_t)(b*NSEQ + q0 + q0r + g + 8))*DM + h*64 + col] =
            make_float2(oacc[nt][2]*inv1, oacc[nt][3]*inv1);
    }
}

// ---------------- out init ----------------
__global__ void init_out_kernel(float* __restrict__ out, const float* __restrict__ b2)
{
    int i = blockIdx.x*256 + threadIdx.x;
    out[i] = b2[0];
}

// ---------------- host launch ----------------
extern "C" void kernel_launch(void* const* d_in, const int* in_sizes, int n_in,
                              void* d_out, int out_size)
{
    const float* sparse_coords = (const float*)d_in[0];
    const float* sparse_values = (const float*)d_in[1];
    const float* query_coords  = (const float*)d_in[2];
    const float* t_in          = (const float*)d_in[3];
    const float* noise         = (const float*)d_in[4];
    const float* B_f           = (const float*)d_in[5];
    const float* Wq_in         = (const float*)d_in[6];
    const float* bq_in         = (const float*)d_in[7];
    const float* Wi_in         = (const float*)d_in[8];
    const float* bi_in         = (const float*)d_in[9];
    const float* A_log         = (const float*)d_in[10];
    const float* Bw            = (const float*)d_in[11];
    const float* Cw            = (const float*)d_in[12];
    const float* Dp            = (const float*)d_in[13];
    const float* ln_g          = (const float*)d_in[14];
    const float* ln_b          = (const float*)d_in[15];
    const float* gate_w        = (const float*)d_in[16];
    const float* gate_b        = (const float*)d_in[17];
    const float* in_proj_w     = (const float*)d_in[18];
    const float* in_proj_b     = (const float*)d_in[19];
    const float* out_w         = (const float*)d_in[20];
    const float* out_b         = (const float*)d_in[21];
    const float* dec_w1        = (const float*)d_in[22];
    const float* dec_b1        = (const float*)d_in[23];
    const float* dec_w2        = (const float*)d_in[24];
    const float* dec_b2        = (const float*)d_in[25];
    float* out = (float*)d_out;

    float *p_seq, *p_xn, *p_gate, *p_bu, *p_hs, *p_q, *p_kv, *p_att, *p_wc, *p_bc;
    unsigned *p_wh, *p_wl;
    cudaGetSymbolAddress((void**)&p_seq, g_seq);
    cudaGetSymbolAddress((void**)&p_xn,  g_xn);
    cudaGetSymbolAddress((void**)&p_gate,g_gate);
    cudaGetSymbolAddress((void**)&p_bu,  g_bu);
    cudaGetSymbolAddress((void**)&p_hs,  g_hs);
    cudaGetSymbolAddress((void**)&p_q,   g_q);
    cudaGetSymbolAddress((void**)&p_kv,  g_kv);
    cudaGetSymbolAddress((void**)&p_att, g_att);
    cudaGetSymbolAddress((void**)&p_wc,  g_wc);
    cudaGetSymbolAddress((void**)&p_bc,  g_bc);
    cudaGetSymbolAddress((void**)&p_wh,  g_wh);
    cudaGetSymbolAddress((void**)&p_wl,  g_wl);

    cudaFuncSetAttribute(attn_kernel, cudaFuncAttributeMaxDynamicSharedMemorySize, ATT_SMEM);

    int ntok_all = BATCH*NTOK;          // 32768
    int nq_all   = BATCH*NSEQ;          // 16384
    const int BIGR = 1 << 30;

    // prep: out init + weight pack + fold (out untouched until dec gemm)
    init_out_kernel<<<nq_all/256, 256>>>(out, dec_b2);
    pack_kernel<<<(131072+255)/256, 256>>>(gate_w,    p_wh + OFF_GATE,   p_wl + OFF_GATE,   131072);
    pack_kernel<<<( 98304+255)/256, 256>>>(in_proj_w, p_wh + OFF_INPROJ, p_wl + OFF_INPROJ,  98304);
    comb_wb_kernel<<<DM, DM>>>(dec_w1, out_w, out_b, dec_b1, p_wc, p_bc);
    pack_kernel<<<(32768+255)/256, 256>>>(p_wc, p_wh + OFF_DEC, p_wl + OFF_DEC, 32768);

    embed_ln_bu_kernel<<<ntok_all, 256>>>(sparse_coords, sparse_values, query_coords, t_in,
                                          noise, B_f, Wq_in, bq_in, Wi_in, bi_in,
                                          ln_g, ln_b, Bw, p_seq, p_xn, p_bu);

    for (int l = 0; l < NLAYER; l++) {
        gemm_tc<<<dim3(2, ntok_all/128 + 64), 256>>>(p_xn,
                                                p_wh + OFF_GATE + l*32768, p_wl + OFF_GATE + l*32768,
                                                gate_b + l*DM, p_gate, nullptr,
                                                A_log + l*NSTATE, p_bu, p_hs,
                                                BIGR, 0, 0, DM, 1);
        if (l < NLAYER-1) {
            ssm_ln_bu_kernel<<<ntok_all, 256>>>(Cw + l*DM*NSTATE, Dp + l*DM,
                                                p_xn, p_hs, p_gate, p_seq,
                                                ln_g + (l+1)*DM, ln_b + (l+1)*DM,
                                                Bw + (l+1)*NSTATE*DM,
                                                p_xn, p_bu);
        } else {
            ssm_out_kernel<<<ntok_all, 256>>>(Cw + l*DM*NSTATE, Dp + l*DM,
                                              p_xn, p_hs, p_gate, p_seq);
        }
    }

    // q projection (query-half rows)
    gemm_tc<<<dim3(2, nq_all/128), 256>>>(p_seq, p_wh + OFF_INPROJ, p_wl + OFF_INPROJ,
                                          in_proj_b, p_q, nullptr, nullptr, nullptr, nullptr,
                                          NSEQ, NTOK, NSEQ, DM, 0);
    // fused k|v projection: N=512, input-half rows, C=[row][512]
    gemm_tc<<<dim3(4, nq_all/128), 256>>>(p_seq, p_wh + OFF_INPROJ + 32768, p_wl + OFF_INPROJ + 32768,
                                          in_proj_b + DM, p_kv, nullptr, nullptr, nullptr, nullptr,
                                          NSEQ, NTOK, 0, KVLD, 0);

    attn_kernel<<<dim3(16, 4, BATCH), 256, ATT_SMEM>>>(p_q, p_kv, p_att);

    gemm_tc<<<dim3(2, nq_all/128), 256>>>(p_att, p_wh + OFF_DEC, p_wl + OFF_DEC,
                                          p_bc, out, dec_w2, nullptr, nullptr, nullptr,
                                          BIGR, 0, 0, DM, 3);
}